// round 1
// baseline (speedup 1.0000x reference)
#include <cuda_runtime.h>
#include <math.h>
#include <math_constants.h>

// Problem constants
#define TOK 4096   // B*S
#define Dm  1024
#define Hh  16
#define HDim 64
#define Ff  4096
#define Ss  2048

// ---------------- scratch (device globals; no cudaMalloc allowed) ----------
__device__ float g_h  [TOK*Dm];
__device__ float g_q  [TOK*Dm];
__device__ float g_k  [TOK*Dm];
__device__ float g_v  [TOK*Dm];
__device__ float g_ctx[TOK*Dm];
__device__ float g_x2 [TOK*Dm];
__device__ float g_a1 [TOK*Ff];   // also reused as router logits (TOK x 64)
__device__ float g_a2 [TOK*Ff];
__device__ int   g_node[TOK*Hh];
__device__ float g_pos [TOK*Hh];

// ---------------- fast exp (FMA pipe only; avoids MUFU bottleneck) ---------
__device__ __forceinline__ float fexp(float x) {
    x = fminf(fmaxf(x, -87.0f), 88.0f);
    float y = x * 1.4426950408889634f;     // x * log2(e)
    float n = rintf(y);
    float f = y - n;                       // f in [-0.5, 0.5]
    float p = 1.3333558146e-3f;            // 2^f Taylor (ln2 powers)
    p = fmaf(p, f, 9.6181291076e-3f);
    p = fmaf(p, f, 5.5504108665e-2f);
    p = fmaf(p, f, 2.4022650696e-1f);
    p = fmaf(p, f, 6.9314718056e-1f);
    p = fmaf(p, f, 1.0f);
    int ni = (int)n;
    return p * __int_as_float((ni + 127) << 23);
}

// ---------------- rmsnorm: one block per row of 1024 -----------------------
__global__ void rmsnorm_k(const float* __restrict__ x, const float* __restrict__ w,
                          float* __restrict__ out) {
    int row = blockIdx.x;
    const float4* xr = (const float4*)(x + (size_t)row * Dm);
    float4 v = xr[threadIdx.x];
    float ss = v.x*v.x + v.y*v.y + v.z*v.z + v.w*v.w;
    #pragma unroll
    for (int o = 16; o; o >>= 1) ss += __shfl_xor_sync(0xffffffffu, ss, o);
    __shared__ float sws[8];
    int lane = threadIdx.x & 31, wid = threadIdx.x >> 5;
    if (lane == 0) sws[wid] = ss;
    __syncthreads();
    if (threadIdx.x == 0) {
        float t = 0.f;
        #pragma unroll
        for (int i = 0; i < 8; i++) t += sws[i];
        sws[0] = rsqrtf(t * (1.0f / Dm) + 1e-6f);
    }
    __syncthreads();
    float inv = sws[0];
    float4 wv = ((const float4*)w)[threadIdx.x];
    float4 o4;
    o4.x = v.x * inv * wv.x; o4.y = v.y * inv * wv.y;
    o4.z = v.z * inv * wv.z; o4.w = v.w * inv * wv.w;
    ((float4*)(out + (size_t)row * Dm))[threadIdx.x] = o4;
}

// ---------------- SGEMM: C[MxN] = A[MxK](row) * B[KxN](row) (+R) -----------
__global__ __launch_bounds__(256, 2)
void sgemm_k(const float* __restrict__ A, const float* __restrict__ B,
             const float* __restrict__ R, float* __restrict__ C,
             int M, int N, int K) {
    __shared__ float As[16][128];
    __shared__ float Bs[16][128];
    int tid = threadIdx.x;
    int tx = tid & 15, ty = tid >> 4;          // 16x16 thread grid, 8x8 micro
    int m0 = blockIdx.y * 128, n0 = blockIdx.x * 128;

    float acc[8][8];
    #pragma unroll
    for (int i = 0; i < 8; i++)
        #pragma unroll
        for (int j = 0; j < 8; j++) acc[i][j] = 0.f;

    for (int k0 = 0; k0 < K; k0 += 16) {
        #pragma unroll
        for (int r = 0; r < 2; ++r) {
            int e = tid + r * 256;             // 0..511
            int arow = e >> 2;                 // 0..127
            int acol = (e & 3) * 4;            // 0,4,8,12
            float4 a = *(const float4*)(A + (size_t)(m0 + arow) * K + k0 + acol);
            As[acol + 0][arow] = a.x; As[acol + 1][arow] = a.y;
            As[acol + 2][arow] = a.z; As[acol + 3][arow] = a.w;
        }
        #pragma unroll
        for (int r = 0; r < 2; ++r) {
            int e = tid + r * 256;
            int brow = e >> 5;                 // 0..15
            int bcol = (e & 31) * 4;           // 0..124
            int gc = n0 + bcol;
            float4 bv = make_float4(0.f, 0.f, 0.f, 0.f);
            if (gc < N) bv = *(const float4*)(B + (size_t)(k0 + brow) * N + gc);
            *(float4*)&Bs[brow][bcol] = bv;
        }
        __syncthreads();
        #pragma unroll
        for (int kk = 0; kk < 16; ++kk) {
            float af[8], bf[8];
            *(float4*)(af)     = *(const float4*)&As[kk][ty * 8];
            *(float4*)(af + 4) = *(const float4*)&As[kk][ty * 8 + 4];
            *(float4*)(bf)     = *(const float4*)&Bs[kk][tx * 8];
            *(float4*)(bf + 4) = *(const float4*)&Bs[kk][tx * 8 + 4];
            #pragma unroll
            for (int i = 0; i < 8; i++)
                #pragma unroll
                for (int j = 0; j < 8; j++)
                    acc[i][j] = fmaf(af[i], bf[j], acc[i][j]);
        }
        __syncthreads();
    }

    #pragma unroll
    for (int i = 0; i < 8; i++) {
        int row = m0 + ty * 8 + i;
        int col = n0 + tx * 8;
        if (col + 7 < N) {
            float4 c0 = make_float4(acc[i][0], acc[i][1], acc[i][2], acc[i][3]);
            float4 c1 = make_float4(acc[i][4], acc[i][5], acc[i][6], acc[i][7]);
            if (R) {
                float4 r0 = *(const float4*)(R + (size_t)row * N + col);
                float4 r1 = *(const float4*)(R + (size_t)row * N + col + 4);
                c0.x += r0.x; c0.y += r0.y; c0.z += r0.z; c0.w += r0.w;
                c1.x += r1.x; c1.y += r1.y; c1.z += r1.z; c1.w += r1.w;
            }
            *(float4*)(C + (size_t)row * N + col)     = c0;
            *(float4*)(C + (size_t)row * N + col + 4) = c1;
        } else {
            #pragma unroll
            for (int j = 0; j < 8; j++) {
                if (col + j < N) {
                    float v = acc[i][j];
                    if (R) v += R[(size_t)row * N + col + j];
                    C[(size_t)row * N + col + j] = v;
                }
            }
        }
    }
}

// ---------------- node (argmax over K=4) + pos (exclusive same-node count) --
__global__ void node_pos_k() {
    int b = blockIdx.x >> 4, h = blockIdx.x & 15;
    int t = threadIdx.x;                        // 0..255, 8 tokens each
    __shared__ int cnts[256][4];
    __shared__ int base[256][4];
    int myn[8], posl[8];
    int local[4] = {0, 0, 0, 0};
    #pragma unroll
    for (int j = 0; j < 8; j++) {
        int s = t * 8 + j;
        int tok = b * Ss + s;
        const float* lp = g_a1 + (size_t)tok * 64 + h * 4;
        float l0 = lp[0], l1 = lp[1], l2 = lp[2], l3 = lp[3];
        int n = 0; float bv = l0;
        if (l1 > bv) { bv = l1; n = 1; }
        if (l2 > bv) { bv = l2; n = 2; }
        if (l3 > bv) { bv = l3; n = 3; }
        myn[j] = n;
        posl[j] = local[n];
        local[n]++;
    }
    cnts[t][0] = local[0]; cnts[t][1] = local[1];
    cnts[t][2] = local[2]; cnts[t][3] = local[3];
    __syncthreads();
    if (t == 0) {
        int run[4] = {0, 0, 0, 0};
        for (int i = 0; i < 256; i++)
            #pragma unroll
            for (int v = 0; v < 4; v++) { base[i][v] = run[v]; run[v] += cnts[i][v]; }
    }
    __syncthreads();
    #pragma unroll
    for (int j = 0; j < 8; j++) {
        int s = t * 8 + j;
        int tok = b * Ss + s;
        int n = myn[j];
        g_node[tok * Hh + h] = n;
        g_pos[tok * Hh + h] = (float)(base[t][n] + posl[j]);
    }
}

// ---------------- RoPE (in place, per (token, head), 32 lanes = 32 pairs) --
__global__ void rope_k(float* __restrict__ t) {
    int inst = blockIdx.x * 4 + (threadIdx.x >> 5);   // token*16 + h
    int lane = threadIdx.x & 31;
    int tok = inst >> 4, h = inst & 15;
    float pos = g_pos[inst];
    // 10000^(-lane/32) = 2^(-lane * log2(10000)/32)
    float invf = exp2f(-(float)lane * (13.287712379549449f / 32.0f));
    float ang = pos * invf;
    float s, c;
    sincosf(ang, &s, &c);
    float* p = t + (size_t)tok * Dm + h * HDim;
    float t1 = p[lane], t2 = p[lane + 32];
    p[lane]      = t1 * c - t2 * s;
    p[lane + 32] = t2 * c + t1 * s;
}

// ---------------- attention: flash-style, node & causal mask ---------------
// grid (S/128, B*H), 128 threads; dynamic smem: K[64][64], V[64][64], Sc[128][65], nodes[64]
#define ATTN_SMEM ((4096 + 4096 + 128 * 65) * 4 + 64 * 4)
__global__ __launch_bounds__(128)
void attn_k() {
    int bh = blockIdx.y;
    int b = bh >> 4, h = bh & 15;
    int q0 = blockIdx.x * 128;
    int tid = threadIdx.x;
    int qi = q0 + tid;
    int qtok = b * Ss + qi;
    extern __shared__ float sm[];
    float* Ks = sm;
    float* Vs = sm + 4096;
    float* Sc = sm + 8192;
    int* nds = (int*)(sm + 8192 + 128 * 65);

    float qreg[64];
    const float4* qp = (const float4*)(g_q + (size_t)qtok * Dm + h * HDim);
    #pragma unroll
    for (int d4 = 0; d4 < 16; d4++) {
        float4 v = qp[d4];
        qreg[d4*4+0] = v.x; qreg[d4*4+1] = v.y; qreg[d4*4+2] = v.z; qreg[d4*4+3] = v.w;
    }
    int nq = g_node[qtok * Hh + h];
    float m = -CUDART_INF_F, l = 0.f;
    float acc[64];
    #pragma unroll
    for (int d = 0; d < 64; d++) acc[d] = 0.f;

    int nkt = (q0 >> 6) + 2;   // k tiles covering [0, q0+127]
    for (int kt = 0; kt < nkt; ++kt) {
        int kb = kt * 64;
        __syncthreads();       // protect K/V reuse across iterations
        for (int e = tid; e < 1024; e += 128) {      // 64 rows x 16 float4
            int r = e >> 4, c = (e & 15) * 4;
            int ktok = b * Ss + kb + r;
            *(float4*)&Ks[r * 64 + c] = *(const float4*)(g_k + (size_t)ktok * Dm + h * HDim + c);
            *(float4*)&Vs[r * 64 + c] = *(const float4*)(g_v + (size_t)ktok * Dm + h * HDim + c);
        }
        if (tid < 64) nds[tid] = g_node[(size_t)(b * Ss + kb + tid) * Hh + h];
        __syncthreads();

        float tmax = -CUDART_INF_F;
        #pragma unroll 1
        for (int kk = 0; kk < 64; ++kk) {
            int ki = kb + kk;
            float s = -1e30f;
            if (ki <= qi && nds[kk] == nq) {
                float s0 = 0.f, s1 = 0.f, s2 = 0.f, s3 = 0.f;
                const float4* kr = (const float4*)&Ks[kk * 64];
                #pragma unroll
                for (int d4 = 0; d4 < 16; d4++) {
                    float4 kv = kr[d4];
                    s0 = fmaf(qreg[d4*4+0], kv.x, s0);
                    s1 = fmaf(qreg[d4*4+1], kv.y, s1);
                    s2 = fmaf(qreg[d4*4+2], kv.z, s2);
                    s3 = fmaf(qreg[d4*4+3], kv.w, s3);
                }
                s = ((s0 + s1) + (s2 + s3)) * 0.125f;
            }
            Sc[tid * 65 + kk] = s;
            tmax = fmaxf(tmax, s);
        }
        if (tmax > -1e29f) {
            float nm = fmaxf(m, tmax);
            float scl = fexp(m - nm);
            l *= scl;
            #pragma unroll
            for (int d = 0; d < 64; d++) acc[d] *= scl;
            #pragma unroll 1
            for (int kk = 0; kk < 64; ++kk) {
                float p = fexp(Sc[tid * 65 + kk] - nm);
                l += p;
                const float4* vr = (const float4*)&Vs[kk * 64];
                #pragma unroll
                for (int d4 = 0; d4 < 16; d4++) {
                    float4 vv = vr[d4];
                    acc[d4*4+0] = fmaf(p, vv.x, acc[d4*4+0]);
                    acc[d4*4+1] = fmaf(p, vv.y, acc[d4*4+1]);
                    acc[d4*4+2] = fmaf(p, vv.z, acc[d4*4+2]);
                    acc[d4*4+3] = fmaf(p, vv.w, acc[d4*4+3]);
                }
            }
            m = nm;
        }
    }
    float inv = 1.f / l;
    float* op = g_ctx + (size_t)qtok * Dm + h * HDim;
    #pragma unroll
    for (int d4 = 0; d4 < 16; d4++) {
        float4 o;
        o.x = acc[d4*4+0] * inv; o.y = acc[d4*4+1] * inv;
        o.z = acc[d4*4+2] * inv; o.w = acc[d4*4+3] * inv;
        *(float4*)(op + d4 * 4) = o;
    }
}

// ---------------- SwiGLU elementwise: a1 = silu(a1) * a2 -------------------
__global__ void silu_mul_k() {
    size_t i = (size_t)blockIdx.x * 256 + threadIdx.x;   // float4 index
    float4 a = ((const float4*)g_a1)[i];
    float4 c = ((const float4*)g_a2)[i];
    a.x = a.x / (1.f + fexp(-a.x)) * c.x;
    a.y = a.y / (1.f + fexp(-a.y)) * c.y;
    a.z = a.z / (1.f + fexp(-a.z)) * c.z;
    a.w = a.w / (1.f + fexp(-a.w)) * c.w;
    ((float4*)g_a1)[i] = a;
}

// ---------------- host launcher --------------------------------------------
extern "C" void kernel_launch(void* const* d_in, const int* in_sizes, int n_in,
                              void* d_out, int out_size) {
    const float* x      = (const float*)d_in[0];
    const float* attn_w = (const float*)d_in[1];
    const float* ffn_w  = (const float*)d_in[2];
    const float* Wq     = (const float*)d_in[3];
    const float* Wk     = (const float*)d_in[4];
    const float* Wv     = (const float*)d_in[5];
    const float* Wo     = (const float*)d_in[6];
    const float* Wr     = (const float*)d_in[7];
    const float* w1     = (const float*)d_in[8];
    const float* w2     = (const float*)d_in[9];
    const float* w3     = (const float*)d_in[10];
    float* out = (float*)d_out;

    float *p_h, *p_q, *p_k, *p_v, *p_ctx, *p_x2, *p_a1, *p_a2;
    cudaGetSymbolAddress((void**)&p_h,   g_h);
    cudaGetSymbolAddress((void**)&p_q,   g_q);
    cudaGetSymbolAddress((void**)&p_k,   g_k);
    cudaGetSymbolAddress((void**)&p_v,   g_v);
    cudaGetSymbolAddress((void**)&p_ctx, g_ctx);
    cudaGetSymbolAddress((void**)&p_x2,  g_x2);
    cudaGetSymbolAddress((void**)&p_a1,  g_a1);
    cudaGetSymbolAddress((void**)&p_a2,  g_a2);
    cudaFuncSetAttribute(attn_k, cudaFuncAttributeMaxDynamicSharedMemorySize, ATTN_SMEM);

    // 1. h = rmsnorm(x, attn_norm_w)
    rmsnorm_k<<<TOK, 256>>>(x, attn_w, p_h);

    // 2. q/k/v = h @ Wq/Wk/Wv ; logits = h @ Wr
    dim3 gq(Dm / 128, TOK / 128);
    sgemm_k<<<gq, 256>>>(p_h, Wq, nullptr, p_q, TOK, Dm, Dm);
    sgemm_k<<<gq, 256>>>(p_h, Wk, nullptr, p_k, TOK, Dm, Dm);
    sgemm_k<<<gq, 256>>>(p_h, Wv, nullptr, p_v, TOK, Dm, Dm);
    dim3 gr(1, TOK / 128);
    sgemm_k<<<gr, 256>>>(p_h, Wr, nullptr, p_a1, TOK, Hh * 4, Dm);

    // 3. node / pos
    node_pos_k<<<32, 256>>>();

    // 4. RoPE on q and k
    rope_k<<<TOK * Hh / 4, 128>>>(p_q);
    rope_k<<<TOK * Hh / 4, 128>>>(p_k);

    // 5. masked attention -> ctx
    attn_k<<<dim3(Ss / 128, 2 * Hh), 128, ATTN_SMEM>>>();

    // 6. x2 = x + ctx @ Wo
    sgemm_k<<<gq, 256>>>(p_ctx, Wo, x, p_x2, TOK, Dm, Dm);

    // 7. h2 = rmsnorm(x2, ffn_norm_w)
    rmsnorm_k<<<TOK, 256>>>(p_x2, ffn_w, p_h);

    // 8. FFN
    dim3 gf(Ff / 128, TOK / 128);
    sgemm_k<<<gf, 256>>>(p_h, w1, nullptr, p_a1, TOK, Ff, Dm);
    sgemm_k<<<gf, 256>>>(p_h, w2, nullptr, p_a2, TOK, Ff, Dm);
    silu_mul_k<<<TOK * Ff / 4 / 256, 256>>>();

    // 9. out = x2 + (silu(a1)*a2) @ w3
    sgemm_k<<<gq, 256>>>(p_a1, w3, p_x2, out, TOK, Dm, Ff);
}

// round 3
// speedup vs baseline: 1.8055x; 1.8055x over previous
#include <cuda_runtime.h>
#include <cuda_bf16.h>
#include <math.h>
#include <math_constants.h>
#include <stdint.h>

#define TOK 4096   // B*S
#define Dm  1024
#define Hh  16
#define HDim 64
#define Ff  4096
#define Ss  2048

// ---------------- fp32 scratch ----------------------------------------------
__device__ float g_h [TOK*Dm];
__device__ float g_q [TOK*Dm];
__device__ float g_k [TOK*Dm];
__device__ float g_v [TOK*Dm];
__device__ float g_x2[TOK*Dm];
__device__ float g_a1[TOK*Ff];   // also router logits (TOK x 64) early on
__device__ float g_a2[TOK*Ff];
__device__ int   g_node[TOK*Hh];
__device__ float g_pos [TOK*Hh];

// ---------------- bf16 split activations ------------------------------------
__device__ __nv_bfloat16 g_hh [TOK*Dm], g_hl [TOK*Dm];
__device__ __nv_bfloat16 g_cxh[TOK*Dm], g_cxl[TOK*Dm];
__device__ __nv_bfloat16 g_s1h[TOK*Ff], g_s1l[TOK*Ff];

// ---------------- bf16 split transposed weights [N,K] -----------------------
__device__ __nv_bfloat16 g_wqh[Dm*Dm], g_wql[Dm*Dm];
__device__ __nv_bfloat16 g_wkh[Dm*Dm], g_wkl[Dm*Dm];
__device__ __nv_bfloat16 g_wvh[Dm*Dm], g_wvl[Dm*Dm];
__device__ __nv_bfloat16 g_woh[Dm*Dm], g_wol[Dm*Dm];
__device__ __nv_bfloat16 g_w1h[Ff*Dm], g_w1l[Ff*Dm];
__device__ __nv_bfloat16 g_w2h[Ff*Dm], g_w2l[Ff*Dm];
__device__ __nv_bfloat16 g_w3h[Dm*Ff], g_w3l[Dm*Ff];
__device__ __nv_bfloat16 g_wrh[128*Dm], g_wrl[128*Dm];  // router, padded to 128 rows

// ---------------- helpers -----------------------------------------------------
__device__ __forceinline__ uint32_t s2u(const void* p) {
    uint32_t a;
    asm("{ .reg .u64 t; cvta.to.shared.u64 t, %1; cvt.u32.u64 %0, t; }" : "=r"(a) : "l"(p));
    return a;
}

#define LDSM4(r, addr) \
    asm volatile("ldmatrix.sync.aligned.m8n8.x4.shared.b16 {%0,%1,%2,%3}, [%4];" \
        : "=r"((r)[0]), "=r"((r)[1]), "=r"((r)[2]), "=r"((r)[3]) : "r"(addr))

#define MMA(d, a, b) \
    asm volatile("mma.sync.aligned.m16n8k16.row.col.f32.bf16.bf16.f32 " \
        "{%0,%1,%2,%3}, {%4,%5,%6,%7}, {%8,%9}, {%0,%1,%2,%3};" \
        : "+f"((d)[0]), "+f"((d)[1]), "+f"((d)[2]), "+f"((d)[3]) \
        : "r"((a)[0]), "r"((a)[1]), "r"((a)[2]), "r"((a)[3]), "r"((b)[0]), "r"((b)[1]))

#define CPASYNC(dst, src) \
    asm volatile("cp.async.cg.shared.global [%0], [%1], 16;" :: "r"(dst), "l"(src))

// ---------------- fast exp (FMA pipe only) ----------------------------------
__device__ __forceinline__ float fexp(float x) {
    x = fminf(fmaxf(x, -87.0f), 88.0f);
    float y = x * 1.4426950408889634f;
    float n = rintf(y);
    float f = y - n;
    float p = 1.3333558146e-3f;
    p = fmaf(p, f, 9.6181291076e-3f);
    p = fmaf(p, f, 5.5504108665e-2f);
    p = fmaf(p, f, 2.4022650696e-1f);
    p = fmaf(p, f, 6.9314718056e-1f);
    p = fmaf(p, f, 1.0f);
    return p * __int_as_float(((int)n + 127) << 23);
}

// ---------------- HMMA split-bf16 GEMM ---------------------------------------
// C[M,*](f32, ld=ldc) = Ah/Al[M,K] @ (Bh/Bl[128-tile rows, K])^T (+R), cols < Nc kept.
// CTA: 128x128 tile, 8 warps (2x4), warp 64x32. K-chunk 32, cp.async 2-stage.
// Smem tile row stride 80B (5 mod 8 -> conflict-free ldmatrix phases).
#define BUF_BYTES 40960
#define GH_SMEM   (2 * BUF_BYTES)

__global__ __launch_bounds__(256, 1)
void gemm_hmma(const __nv_bfloat16* __restrict__ Ah, const __nv_bfloat16* __restrict__ Al,
               const __nv_bfloat16* __restrict__ Bh, const __nv_bfloat16* __restrict__ Bl,
               const float* __restrict__ R, float* __restrict__ C,
               int M, int Nc, int ldc, int K) {
    extern __shared__ char smraw[];
    const int tid  = threadIdx.x;
    const int lane = tid & 31, wid = tid >> 5;
    const int m0 = blockIdx.y * 128, n0 = blockIdx.x * 128;
    const int warp_m = (wid >> 2) * 64, warp_n = (wid & 3) * 32;
    const int nc = K >> 5;
    const uint32_t sb = s2u(smraw);

    const char* gA  = (const char*)Ah + (size_t)m0 * K * 2;
    const char* gAl = (const char*)Al + (size_t)m0 * K * 2;
    const char* gB  = (const char*)Bh + (size_t)n0 * K * 2;
    const char* gBl = (const char*)Bl + (size_t)n0 * K * 2;

    // per-thread load slots: e = tid + i*256 -> row e>>2, 16B col (e&3)
    int lr0 = tid >> 2,          lc0 = (tid & 3) * 16;
    int lr1 = (tid + 256) >> 2,  lc1 = lc0;

    #define ISSUE(buf, kc) do { \
        uint32_t db = sb + (buf) * BUF_BYTES; \
        size_t ko = (size_t)(kc) * 64; \
        uint32_t so0 = lr0 * 80 + lc0, so1 = lr1 * 80 + lc1; \
        size_t go0 = (size_t)lr0 * (K * 2) + ko + lc0; \
        size_t go1 = (size_t)lr1 * (K * 2) + ko + lc1; \
        CPASYNC(db + so0,         gA  + go0); CPASYNC(db + so1,         gA  + go1); \
        CPASYNC(db + 10240 + so0, gAl + go0); CPASYNC(db + 10240 + so1, gAl + go1); \
        CPASYNC(db + 20480 + so0, gB  + go0); CPASYNC(db + 20480 + so1, gB  + go1); \
        CPASYNC(db + 30720 + so0, gBl + go0); CPASYNC(db + 30720 + so1, gBl + go1); \
        asm volatile("cp.async.commit_group;"); \
    } while (0)

    ISSUE(0, 0);
    ISSUE(1, 1);

    float acc[4][4][4];
    #pragma unroll
    for (int i = 0; i < 4; i++)
        #pragma unroll
        for (int j = 0; j < 4; j++)
            #pragma unroll
            for (int q = 0; q < 4; q++) acc[i][j][q] = 0.f;

    // ldmatrix lane addressing
    const int a_row = (lane & 7) + ((lane >> 3) & 1) * 8;   // A: m0..m7 | m8..m15 halves
    const int a_cb  = (lane >> 4) * 16;                     // A: k byte half
    const int b_row = (lane & 7) + (lane >> 4) * 8;         // B: n within 16
    const int b_cb  = ((lane >> 3) & 1) * 16;               // B: k byte half

    #pragma unroll 1
    for (int kc = 0; kc < nc; kc++) {
        if (kc + 1 < nc) asm volatile("cp.async.wait_group 1;");
        else             asm volatile("cp.async.wait_group 0;");
        __syncthreads();
        uint32_t db = sb + (kc & 1) * BUF_BYTES;
        #pragma unroll
        for (int ks = 0; ks < 2; ks++) {
            uint32_t ah[4][4], al[4][4], bh[4][2], bl[4][2];
            #pragma unroll
            for (int mt = 0; mt < 4; mt++) {
                uint32_t ad = db + (warp_m + mt * 16 + a_row) * 80 + a_cb + ks * 32;
                LDSM4(ah[mt], ad);
                LDSM4(al[mt], ad + 10240);
            }
            #pragma unroll
            for (int p = 0; p < 2; p++) {
                uint32_t bd = db + 20480 + (warp_n + p * 16 + b_row) * 80 + b_cb + ks * 32;
                LDSM4(&bh[2 * p][0], bd);          // fills bh[2p][0..1], bh[2p+1][0..1]
                LDSM4(&bl[2 * p][0], bd + 10240);
            }
            #pragma unroll
            for (int mt = 0; mt < 4; mt++)
                #pragma unroll
                for (int nt = 0; nt < 4; nt++) MMA(acc[mt][nt], ah[mt], bh[nt]);
            #pragma unroll
            for (int mt = 0; mt < 4; mt++)
                #pragma unroll
                for (int nt = 0; nt < 4; nt++) MMA(acc[mt][nt], ah[mt], bl[nt]);
            #pragma unroll
            for (int mt = 0; mt < 4; mt++)
                #pragma unroll
                for (int nt = 0; nt < 4; nt++) MMA(acc[mt][nt], al[mt], bh[nt]);
        }
        __syncthreads();
        if (kc + 2 < nc) ISSUE(kc & 1, kc + 2);
    }
    #undef ISSUE

    // epilogue: c0=(g,2c) c1=(g,2c+1) c2=(g+8,2c) c3=(g+8,2c+1)
    const int g  = lane >> 2;
    const int cc = (lane & 3) * 2;
    #pragma unroll
    for (int mt = 0; mt < 4; mt++) {
        int row0 = m0 + warp_m + mt * 16 + g;
        #pragma unroll
        for (int nt = 0; nt < 4; nt++) {
            int col = n0 + warp_n + nt * 8 + cc;
            if (col < Nc) {
                float2 v0 = make_float2(acc[mt][nt][0], acc[mt][nt][1]);
                float2 v1 = make_float2(acc[mt][nt][2], acc[mt][nt][3]);
                if (R) {
                    float2 r0 = *(const float2*)(R + (size_t)row0 * ldc + col);
                    float2 r1 = *(const float2*)(R + (size_t)(row0 + 8) * ldc + col);
                    v0.x += r0.x; v0.y += r0.y; v1.x += r1.x; v1.y += r1.y;
                }
                *(float2*)(C + (size_t)row0 * ldc + col)       = v0;
                *(float2*)(C + (size_t)(row0 + 8) * ldc + col) = v1;
            }
        }
    }
}

// ---------------- weight transpose + bf16 split ------------------------------
// W[Kd,Nd] fp32 row-major -> Th/Tl[Nd,Kd] bf16 row-major
__global__ void wsplit_k(const float* __restrict__ W, __nv_bfloat16* __restrict__ Th,
                         __nv_bfloat16* __restrict__ Tl, int Kd, int Nd) {
    __shared__ float t[32][33];
    int n0 = blockIdx.x * 32, k0 = blockIdx.y * 32;
    int tx = threadIdx.x, ty = threadIdx.y;
    #pragma unroll
    for (int i = 0; i < 4; i++)
        t[ty + i * 8][tx] = W[(size_t)(k0 + ty + i * 8) * Nd + n0 + tx];
    __syncthreads();
    #pragma unroll
    for (int i = 0; i < 4; i++) {
        int r = ty + i * 8;
        float v = t[tx][r];
        __nv_bfloat16 hb = __float2bfloat16(v);
        size_t o = (size_t)(n0 + r) * Kd + k0 + tx;
        Th[o] = hb;
        Tl[o] = __float2bfloat16(v - __bfloat162float(hb));
    }
}

// ---------------- rmsnorm (+ bf16 split outputs) -----------------------------
__global__ void rmsnorm_k(const float* __restrict__ x, const float* __restrict__ w,
                          float* __restrict__ out,
                          __nv_bfloat16* __restrict__ oh, __nv_bfloat16* __restrict__ ol) {
    int row = blockIdx.x;
    const float4* xr = (const float4*)(x + (size_t)row * Dm);
    float4 v = xr[threadIdx.x];
    float ss = v.x*v.x + v.y*v.y + v.z*v.z + v.w*v.w;
    #pragma unroll
    for (int o = 16; o; o >>= 1) ss += __shfl_xor_sync(0xffffffffu, ss, o);
    __shared__ float sws[8];
    int lane = threadIdx.x & 31, wid = threadIdx.x >> 5;
    if (lane == 0) sws[wid] = ss;
    __syncthreads();
    if (threadIdx.x == 0) {
        float t = 0.f;
        #pragma unroll
        for (int i = 0; i < 8; i++) t += sws[i];
        sws[0] = rsqrtf(t * (1.0f / Dm) + 1e-6f);
    }
    __syncthreads();
    float inv = sws[0];
    float4 wv = ((const float4*)w)[threadIdx.x];
    float4 o4;
    o4.x = v.x * inv * wv.x; o4.y = v.y * inv * wv.y;
    o4.z = v.z * inv * wv.z; o4.w = v.w * inv * wv.w;
    if (out) ((float4*)(out + (size_t)row * Dm))[threadIdx.x] = o4;
    __nv_bfloat16 h0 = __float2bfloat16(o4.x), h1 = __float2bfloat16(o4.y);
    __nv_bfloat16 h2 = __float2bfloat16(o4.z), h3 = __float2bfloat16(o4.w);
    __nv_bfloat162 H0; H0.x = h0; H0.y = h1;
    __nv_bfloat162 H1; H1.x = h2; H1.y = h3;
    __nv_bfloat162* ph = (__nv_bfloat162*)(oh + (size_t)row * Dm);
    ph[threadIdx.x * 2]     = H0;
    ph[threadIdx.x * 2 + 1] = H1;
    __nv_bfloat162 L0, L1;
    L0.x = __float2bfloat16(o4.x - __bfloat162float(h0));
    L0.y = __float2bfloat16(o4.y - __bfloat162float(h1));
    L1.x = __float2bfloat16(o4.z - __bfloat162float(h2));
    L1.y = __float2bfloat16(o4.w - __bfloat162float(h3));
    __nv_bfloat162* pl = (__nv_bfloat162*)(ol + (size_t)row * Dm);
    pl[threadIdx.x * 2]     = L0;
    pl[threadIdx.x * 2 + 1] = L1;
}

// ---------------- node/pos ----------------------------------------------------
__global__ void node_pos_k() {
    int b = blockIdx.x >> 4, h = blockIdx.x & 15;
    int t = threadIdx.x;
    __shared__ int cnts[256][4];
    __shared__ int base[256][4];
    int myn[8], posl[8];
    int local[4] = {0, 0, 0, 0};
    #pragma unroll
    for (int j = 0; j < 8; j++) {
        int s = t * 8 + j;
        int tok = b * Ss + s;
        const float* lp = g_a1 + (size_t)tok * 64 + h * 4;
        float l0 = lp[0], l1 = lp[1], l2 = lp[2], l3 = lp[3];
        int n = 0; float bv = l0;
        if (l1 > bv) { bv = l1; n = 1; }
        if (l2 > bv) { bv = l2; n = 2; }
        if (l3 > bv) { bv = l3; n = 3; }
        myn[j] = n;
        posl[j] = local[n];
        local[n]++;
    }
    cnts[t][0] = local[0]; cnts[t][1] = local[1];
    cnts[t][2] = local[2]; cnts[t][3] = local[3];
    __syncthreads();
    if (t == 0) {
        int run[4] = {0, 0, 0, 0};
        for (int i = 0; i < 256; i++)
            #pragma unroll
            for (int v = 0; v < 4; v++) { base[i][v] = run[v]; run[v] += cnts[i][v]; }
    }
    __syncthreads();
    #pragma unroll
    for (int j = 0; j < 8; j++) {
        int s = t * 8 + j;
        int tok = b * Ss + s;
        int n = myn[j];
        g_node[tok * Hh + h] = n;
        g_pos[tok * Hh + h] = (float)(base[t][n] + posl[j]);
    }
}

// ---------------- RoPE --------------------------------------------------------
__global__ void rope_k(float* __restrict__ t) {
    int inst = blockIdx.x * 4 + (threadIdx.x >> 5);
    int lane = threadIdx.x & 31;
    int tok = inst >> 4, h = inst & 15;
    float pos = g_pos[inst];
    float invf = exp2f(-(float)lane * (13.287712379549449f / 32.0f));
    float ang = pos * invf;
    float s, c;
    sincosf(ang, &s, &c);
    float* p = t + (size_t)tok * Dm + h * HDim;
    float t1 = p[lane], t2 = p[lane + 32];
    p[lane]      = t1 * c - t2 * s;
    p[lane + 32] = t2 * c + t1 * s;
}

// ---------------- attention ----------------------------------------------------
#define ATTN_SMEM ((4096 + 4096 + 128 * 65) * 4 + 64 * 4)
__global__ __launch_bounds__(128)
void attn_k() {
    int bh = blockIdx.y;
    int b = bh >> 4, h = bh & 15;
    int q0 = blockIdx.x * 128;
    int tid = threadIdx.x;
    int qi = q0 + tid;
    int qtok = b * Ss + qi;
    extern __shared__ float sm[];
    float* Ks = sm;
    float* Vs = sm + 4096;
    float* Sc = sm + 8192;
    int* nds = (int*)(sm + 8192 + 128 * 65);

    float qreg[64];
    const float4* qp = (const float4*)(g_q + (size_t)qtok * Dm + h * HDim);
    #pragma unroll
    for (int d4 = 0; d4 < 16; d4++) {
        float4 v = qp[d4];
        qreg[d4*4+0] = v.x; qreg[d4*4+1] = v.y; qreg[d4*4+2] = v.z; qreg[d4*4+3] = v.w;
    }
    int nq = g_node[qtok * Hh + h];
    float m = -CUDART_INF_F, l = 0.f;
    float acc[64];
    #pragma unroll
    for (int d = 0; d < 64; d++) acc[d] = 0.f;

    int nkt = (q0 >> 6) + 2;
    for (int kt = 0; kt < nkt; ++kt) {
        int kb = kt * 64;
        __syncthreads();
        for (int e = tid; e < 1024; e += 128) {
            int r = e >> 4, c = (e & 15) * 4;
            int ktok = b * Ss + kb + r;
            *(float4*)&Ks[r * 64 + c] = *(const float4*)(g_k + (size_t)ktok * Dm + h * HDim + c);
            *(float4*)&Vs[r * 64 + c] = *(const float4*)(g_v + (size_t)ktok * Dm + h * HDim + c);
        }
        if (tid < 64) nds[tid] = g_node[(size_t)(b * Ss + kb + tid) * Hh + h];
        __syncthreads();

        float tmax = -CUDART_INF_F;
        #pragma unroll 1
        for (int kk = 0; kk < 64; ++kk) {
            int ki = kb + kk;
            float s = -1e30f;
            if (ki <= qi && nds[kk] == nq) {
                float s0 = 0.f, s1 = 0.f, s2 = 0.f, s3 = 0.f;
                const float4* kr = (const float4*)&Ks[kk * 64];
                #pragma unroll
                for (int d4 = 0; d4 < 16; d4++) {
                    float4 kv = kr[d4];
                    s0 = fmaf(qreg[d4*4+0], kv.x, s0);
                    s1 = fmaf(qreg[d4*4+1], kv.y, s1);
                    s2 = fmaf(qreg[d4*4+2], kv.z, s2);
                    s3 = fmaf(qreg[d4*4+3], kv.w, s3);
                }
                s = ((s0 + s1) + (s2 + s3)) * 0.125f;
            }
            Sc[tid * 65 + kk] = s;
            tmax = fmaxf(tmax, s);
        }
        if (tmax > -1e29f) {
            float nm = fmaxf(m, tmax);
            float scl = fexp(m - nm);
            l *= scl;
            #pragma unroll
            for (int d = 0; d < 64; d++) acc[d] *= scl;
            #pragma unroll 1
            for (int kk = 0; kk < 64; ++kk) {
                float p = fexp(Sc[tid * 65 + kk] - nm);
                l += p;
                const float4* vr = (const float4*)&Vs[kk * 64];
                #pragma unroll
                for (int d4 = 0; d4 < 16; d4++) {
                    float4 vv = vr[d4];
                    acc[d4*4+0] = fmaf(p, vv.x, acc[d4*4+0]);
                    acc[d4*4+1] = fmaf(p, vv.y, acc[d4*4+1]);
                    acc[d4*4+2] = fmaf(p, vv.z, acc[d4*4+2]);
                    acc[d4*4+3] = fmaf(p, vv.w, acc[d4*4+3]);
                }
            }
            m = nm;
        }
    }
    float inv = 1.f / l;
    __nv_bfloat162* oh = (__nv_bfloat162*)(g_cxh + (size_t)qtok * Dm + h * HDim);
    __nv_bfloat162* ol = (__nv_bfloat162*)(g_cxl + (size_t)qtok * Dm + h * HDim);
    #pragma unroll
    for (int d2 = 0; d2 < 32; d2++) {
        float v0 = acc[d2*2] * inv, v1 = acc[d2*2+1] * inv;
        __nv_bfloat16 h0 = __float2bfloat16(v0), h1 = __float2bfloat16(v1);
        __nv_bfloat162 H; H.x = h0; H.y = h1;
        oh[d2] = H;
        __nv_bfloat162 L;
        L.x = __float2bfloat16(v0 - __bfloat162float(h0));
        L.y = __float2bfloat16(v1 - __bfloat162float(h1));
        ol[d2] = L;
    }
}

// ---------------- SwiGLU elementwise -> bf16 split ---------------------------
__global__ void silu_mul_k() {
    size_t i = (size_t)blockIdx.x * 256 + threadIdx.x;
    float4 a = ((const float4*)g_a1)[i];
    float4 c = ((const float4*)g_a2)[i];
    float r0 = a.x / (1.f + fexp(-a.x)) * c.x;
    float r1 = a.y / (1.f + fexp(-a.y)) * c.y;
    float r2 = a.z / (1.f + fexp(-a.z)) * c.z;
    float r3 = a.w / (1.f + fexp(-a.w)) * c.w;
    __nv_bfloat16 h0 = __float2bfloat16(r0), h1 = __float2bfloat16(r1);
    __nv_bfloat16 h2 = __float2bfloat16(r2), h3 = __float2bfloat16(r3);
    __nv_bfloat162 H0; H0.x = h0; H0.y = h1;
    __nv_bfloat162 H1; H1.x = h2; H1.y = h3;
    ((__nv_bfloat162*)g_s1h)[i*2]   = H0;
    ((__nv_bfloat162*)g_s1h)[i*2+1] = H1;
    __nv_bfloat162 L0, L1;
    L0.x = __float2bfloat16(r0 - __bfloat162float(h0));
    L0.y = __float2bfloat16(r1 - __bfloat162float(h1));
    L1.x = __float2bfloat16(r2 - __bfloat162float(h2));
    L1.y = __float2bfloat16(r3 - __bfloat162float(h3));
    ((__nv_bfloat162*)g_s1l)[i*2]   = L0;
    ((__nv_bfloat162*)g_s1l)[i*2+1] = L1;
}

// ---------------- host launcher ----------------------------------------------
#define SYM(p, s) do { void* _t; cudaGetSymbolAddress(&_t, s); p = (decltype(p))_t; } while (0)

extern "C" void kernel_launch(void* const* d_in, const int* in_sizes, int n_in,
                              void* d_out, int out_size) {
    const float* x      = (const float*)d_in[0];
    const float* attn_w = (const float*)d_in[1];
    const float* ffn_w  = (const float*)d_in[2];
    const float* Wq     = (const float*)d_in[3];
    const float* Wk     = (const float*)d_in[4];
    const float* Wv     = (const float*)d_in[5];
    const float* Wo     = (const float*)d_in[6];
    const float* Wr     = (const float*)d_in[7];
    const float* w1     = (const float*)d_in[8];
    const float* w2     = (const float*)d_in[9];
    const float* w3     = (const float*)d_in[10];
    float* out = (float*)d_out;

    float *p_q, *p_k, *p_v, *p_x2, *p_a1, *p_a2;
    SYM(p_q, g_q);  SYM(p_k, g_k);  SYM(p_v, g_v);
    SYM(p_x2, g_x2); SYM(p_a1, g_a1); SYM(p_a2, g_a2);
    __nv_bfloat16 *p_hh, *p_hl, *p_cxh, *p_cxl, *p_s1h, *p_s1l;
    SYM(p_hh, g_hh); SYM(p_hl, g_hl); SYM(p_cxh, g_cxh); SYM(p_cxl, g_cxl);
    SYM(p_s1h, g_s1h); SYM(p_s1l, g_s1l);
    __nv_bfloat16 *wqh, *wql, *wkh, *wkl, *wvh, *wvl, *woh, *wol;
    __nv_bfloat16 *w1h, *w1l, *w2h, *w2l, *w3h, *w3l, *wrh, *wrl;
    SYM(wqh, g_wqh); SYM(wql, g_wql); SYM(wkh, g_wkh); SYM(wkl, g_wkl);
    SYM(wvh, g_wvh); SYM(wvl, g_wvl); SYM(woh, g_woh); SYM(wol, g_wol);
    SYM(w1h, g_w1h); SYM(w1l, g_w1l); SYM(w2h, g_w2h); SYM(w2l, g_w2l);
    SYM(w3h, g_w3h); SYM(w3l, g_w3l); SYM(wrh, g_wrh); SYM(wrl, g_wrl);

    cudaFuncSetAttribute(attn_k, cudaFuncAttributeMaxDynamicSharedMemorySize, ATTN_SMEM);
    cudaFuncSetAttribute(gemm_hmma, cudaFuncAttributeMaxDynamicSharedMemorySize, GH_SMEM);

    // zero router-weight pad rows [64,128)
    cudaMemsetAsync(wrh + 64 * Dm, 0, 64 * Dm * sizeof(__nv_bfloat16));
    cudaMemsetAsync(wrl + 64 * Dm, 0, 64 * Dm * sizeof(__nv_bfloat16));

    dim3 tb(32, 8);
    wsplit_k<<<dim3(Dm/32, Dm/32), tb>>>(Wq, wqh, wql, Dm, Dm);
    wsplit_k<<<dim3(Dm/32, Dm/32), tb>>>(Wk, wkh, wkl, Dm, Dm);
    wsplit_k<<<dim3(Dm/32, Dm/32), tb>>>(Wv, wvh, wvl, Dm, Dm);
    wsplit_k<<<dim3(Dm/32, Dm/32), tb>>>(Wo, woh, wol, Dm, Dm);
    wsplit_k<<<dim3(Ff/32, Dm/32), tb>>>(w1, w1h, w1l, Dm, Ff);
    wsplit_k<<<dim3(Ff/32, Dm/32), tb>>>(w2, w2h, w2l, Dm, Ff);
    wsplit_k<<<dim3(Dm/32, Ff/32), tb>>>(w3, w3h, w3l, Ff, Dm);
    wsplit_k<<<dim3(2, Dm/32),    tb>>>(Wr, wrh, wrl, Dm, 64);

    // 1. h = rmsnorm(x) -> bf16 split
    rmsnorm_k<<<TOK, 256>>>(x, attn_w, nullptr, p_hh, p_hl);

    // 2. q/k/v + router logits via HMMA
    dim3 gq(Dm / 128, TOK / 128);
    gemm_hmma<<<gq, 256, GH_SMEM>>>(p_hh, p_hl, wqh, wql, nullptr, p_q, TOK, Dm, Dm, Dm);
    gemm_hmma<<<gq, 256, GH_SMEM>>>(p_hh, p_hl, wkh, wkl, nullptr, p_k, TOK, Dm, Dm, Dm);
    gemm_hmma<<<gq, 256, GH_SMEM>>>(p_hh, p_hl, wvh, wvl, nullptr, p_v, TOK, Dm, Dm, Dm);
    gemm_hmma<<<dim3(1, TOK / 128), 256, GH_SMEM>>>(p_hh, p_hl, wrh, wrl, nullptr, p_a1,
                                                    TOK, 64, 64, Dm);

    // 3. node / pos, RoPE
    node_pos_k<<<32, 256>>>();
    rope_k<<<TOK * Hh / 4, 128>>>(p_q);
    rope_k<<<TOK * Hh / 4, 128>>>(p_k);

    // 4. attention -> ctx (bf16 split)
    attn_k<<<dim3(Ss / 128, 2 * Hh), 128, ATTN_SMEM>>>();

    // 5. x2 = x + ctx @ Wo
    gemm_hmma<<<gq, 256, GH_SMEM>>>(p_cxh, p_cxl, woh, wol, x, p_x2, TOK, Dm, Dm, Dm);

    // 6. h2 = rmsnorm(x2) -> bf16 split
    rmsnorm_k<<<TOK, 256>>>(p_x2, ffn_w, nullptr, p_hh, p_hl);

    // 7. FFN up projections
    dim3 gf(Ff / 128, TOK / 128);
    gemm_hmma<<<gf, 256, GH_SMEM>>>(p_hh, p_hl, w1h, w1l, nullptr, p_a1, TOK, Ff, Ff, Dm);
    gemm_hmma<<<gf, 256, GH_SMEM>>>(p_hh, p_hl, w2h, w2l, nullptr, p_a2, TOK, Ff, Ff, Dm);
    silu_mul_k<<<TOK * Ff / 4 / 256, 256>>>();

    // 8. out = x2 + (silu(a1)*a2) @ w3
    gemm_hmma<<<gq, 256, GH_SMEM>>>(p_s1h, p_s1l, w3h, w3l, p_x2, out, TOK, Dm, Dm, Ff);
}

// round 4
// speedup vs baseline: 2.5227x; 1.3972x over previous
#include <cuda_runtime.h>
#include <cuda_bf16.h>
#include <math.h>
#include <math_constants.h>
#include <stdint.h>

#define TOK 4096   // B*S
#define Dm  1024
#define Hh  16
#define HDim 64
#define Ff  4096
#define Ss  2048
#define NQKV 3200  // q(1024) k(1024) v(1024) router(64) pad(64)

// ---------------- fp32 scratch ----------------------------------------------
__device__ float g_qkvr[TOK*NQKV];
__device__ float g_x2 [TOK*Dm];
__device__ float g_a12[TOK*2*Ff];
__device__ int   g_node[TOK*Hh];
__device__ float g_pos [TOK*Hh];
__device__ int   g_start [32*4];        // per (b,h): node partition starts
__device__ int   g_qstart[32*Ss];       // per slot: its partition start
__device__ int   g_orig  [32*Ss];       // per slot: original token index
__device__ float g_qp[32*Ss*HDim];      // partitioned q (rope'd)
__device__ float g_kp[32*Ss*HDim];      // partitioned k (rope'd)
__device__ float g_vp[32*Ss*HDim];      // partitioned v

// ---------------- bf16 split activations ------------------------------------
__device__ __nv_bfloat16 g_hh [TOK*Dm], g_hl [TOK*Dm];
__device__ __nv_bfloat16 g_cxh[TOK*Dm], g_cxl[TOK*Dm];
__device__ __nv_bfloat16 g_s1h[TOK*Ff], g_s1l[TOK*Ff];

// ---------------- bf16 split transposed weights [N,K] -----------------------
__device__ __nv_bfloat16 g_wAh[NQKV*Dm], g_wAl[NQKV*Dm];   // Wq|Wk|Wv|Wr|0
__device__ __nv_bfloat16 g_woh[Dm*Dm],   g_wol[Dm*Dm];
__device__ __nv_bfloat16 g_w12h[2*Ff*Dm], g_w12l[2*Ff*Dm]; // w1|w2
__device__ __nv_bfloat16 g_w3h[Dm*Ff],   g_w3l[Dm*Ff];

// ---------------- helpers -----------------------------------------------------
__device__ __forceinline__ uint32_t s2u(const void* p) {
    uint32_t a;
    asm("{ .reg .u64 t; cvta.to.shared.u64 t, %1; cvt.u32.u64 %0, t; }" : "=r"(a) : "l"(p));
    return a;
}

#define LDSM4(r, addr) \
    asm volatile("ldmatrix.sync.aligned.m8n8.x4.shared.b16 {%0,%1,%2,%3}, [%4];" \
        : "=r"((r)[0]), "=r"((r)[1]), "=r"((r)[2]), "=r"((r)[3]) : "r"(addr))

#define MMA(d, a, b) \
    asm volatile("mma.sync.aligned.m16n8k16.row.col.f32.bf16.bf16.f32 " \
        "{%0,%1,%2,%3}, {%4,%5,%6,%7}, {%8,%9}, {%0,%1,%2,%3};" \
        : "+f"((d)[0]), "+f"((d)[1]), "+f"((d)[2]), "+f"((d)[3]) \
        : "r"((a)[0]), "r"((a)[1]), "r"((a)[2]), "r"((a)[3]), "r"((b)[0]), "r"((b)[1]))

#define CPASYNC(dst, src) \
    asm volatile("cp.async.cg.shared.global [%0], [%1], 16;" :: "r"(dst), "l"(src))

// ---------------- fast exp (FMA pipe only) ----------------------------------
__device__ __forceinline__ float fexp(float x) {
    x = fminf(fmaxf(x, -87.0f), 88.0f);
    float y = x * 1.4426950408889634f;
    float n = rintf(y);
    float f = y - n;
    float p = 1.3333558146e-3f;
    p = fmaf(p, f, 9.6181291076e-3f);
    p = fmaf(p, f, 5.5504108665e-2f);
    p = fmaf(p, f, 2.4022650696e-1f);
    p = fmaf(p, f, 6.9314718056e-1f);
    p = fmaf(p, f, 1.0f);
    return p * __int_as_float(((int)n + 127) << 23);
}

// ---------------- HMMA split-bf16 GEMM, 3-stage cp.async ---------------------
#define BUF_BYTES 40960
#define GH_SMEM   (3 * BUF_BYTES)

__global__ __launch_bounds__(256, 1)
void gemm_hmma(const __nv_bfloat16* __restrict__ Ah, const __nv_bfloat16* __restrict__ Al,
               const __nv_bfloat16* __restrict__ Bh, const __nv_bfloat16* __restrict__ Bl,
               const float* __restrict__ R, float* __restrict__ C,
               int M, int Nc, int ldc, int K) {
    extern __shared__ char smraw[];
    const int tid  = threadIdx.x;
    const int lane = tid & 31, wid = tid >> 5;
    const int m0 = blockIdx.y * 128, n0 = blockIdx.x * 128;
    const int warp_m = (wid >> 2) * 64, warp_n = (wid & 3) * 32;
    const int nc = K >> 5;
    const uint32_t sb = s2u(smraw);

    const char* gA  = (const char*)Ah + (size_t)m0 * K * 2;
    const char* gAl = (const char*)Al + (size_t)m0 * K * 2;
    const char* gB  = (const char*)Bh + (size_t)n0 * K * 2;
    const char* gBl = (const char*)Bl + (size_t)n0 * K * 2;

    int lr0 = tid >> 2,          lc0 = (tid & 3) * 16;
    int lr1 = (tid + 256) >> 2,  lc1 = lc0;

    #define ISSUE(buf, kc) do { \
        uint32_t db = sb + (buf) * BUF_BYTES; \
        size_t ko = (size_t)(kc) * 64; \
        uint32_t so0 = lr0 * 80 + lc0, so1 = lr1 * 80 + lc1; \
        size_t go0 = (size_t)lr0 * (K * 2) + ko + lc0; \
        size_t go1 = (size_t)lr1 * (K * 2) + ko + lc1; \
        CPASYNC(db + so0,         gA  + go0); CPASYNC(db + so1,         gA  + go1); \
        CPASYNC(db + 10240 + so0, gAl + go0); CPASYNC(db + 10240 + so1, gAl + go1); \
        CPASYNC(db + 20480 + so0, gB  + go0); CPASYNC(db + 20480 + so1, gB  + go1); \
        CPASYNC(db + 30720 + so0, gBl + go0); CPASYNC(db + 30720 + so1, gBl + go1); \
        asm volatile("cp.async.commit_group;"); \
    } while (0)

    ISSUE(0, 0);
    ISSUE(1, 1);
    ISSUE(2, 2);

    float acc[4][4][4];
    #pragma unroll
    for (int i = 0; i < 4; i++)
        #pragma unroll
        for (int j = 0; j < 4; j++)
            #pragma unroll
            for (int q = 0; q < 4; q++) acc[i][j][q] = 0.f;

    const int a_row = (lane & 7) + ((lane >> 3) & 1) * 8;
    const int a_cb  = (lane >> 4) * 16;
    const int b_row = (lane & 7) + (lane >> 4) * 8;
    const int b_cb  = ((lane >> 3) & 1) * 16;

    int buf = 0;
    #pragma unroll 1
    for (int kc = 0; kc < nc; kc++) {
        if (kc + 3 <= nc)      asm volatile("cp.async.wait_group 2;");
        else if (kc + 2 <= nc) asm volatile("cp.async.wait_group 1;");
        else                   asm volatile("cp.async.wait_group 0;");
        __syncthreads();
        uint32_t db = sb + buf * BUF_BYTES;
        #pragma unroll
        for (int ks = 0; ks < 2; ks++) {
            uint32_t ah[4][4], al[4][4], bh[4][2], bl[4][2];
            #pragma unroll
            for (int mt = 0; mt < 4; mt++) {
                uint32_t ad = db + (warp_m + mt * 16 + a_row) * 80 + a_cb + ks * 32;
                LDSM4(ah[mt], ad);
                LDSM4(al[mt], ad + 10240);
            }
            #pragma unroll
            for (int p = 0; p < 2; p++) {
                uint32_t bd = db + 20480 + (warp_n + p * 16 + b_row) * 80 + b_cb + ks * 32;
                LDSM4(&bh[2 * p][0], bd);
                LDSM4(&bl[2 * p][0], bd + 10240);
            }
            #pragma unroll
            for (int mt = 0; mt < 4; mt++)
                #pragma unroll
                for (int nt = 0; nt < 4; nt++) MMA(acc[mt][nt], ah[mt], bh[nt]);
            #pragma unroll
            for (int mt = 0; mt < 4; mt++)
                #pragma unroll
                for (int nt = 0; nt < 4; nt++) MMA(acc[mt][nt], ah[mt], bl[nt]);
            #pragma unroll
            for (int mt = 0; mt < 4; mt++)
                #pragma unroll
                for (int nt = 0; nt < 4; nt++) MMA(acc[mt][nt], al[mt], bh[nt]);
        }
        __syncthreads();
        if (kc + 3 < nc) ISSUE(buf, kc + 3);
        buf = (buf == 2) ? 0 : buf + 1;
    }
    #undef ISSUE

    const int g  = lane >> 2;
    const int cc = (lane & 3) * 2;
    #pragma unroll
    for (int mt = 0; mt < 4; mt++) {
        int row0 = m0 + warp_m + mt * 16 + g;
        #pragma unroll
        for (int nt = 0; nt < 4; nt++) {
            int col = n0 + warp_n + nt * 8 + cc;
            if (col < Nc) {
                float2 v0 = make_float2(acc[mt][nt][0], acc[mt][nt][1]);
                float2 v1 = make_float2(acc[mt][nt][2], acc[mt][nt][3]);
                if (R) {
                    float2 r0 = *(const float2*)(R + (size_t)row0 * ldc + col);
                    float2 r1 = *(const float2*)(R + (size_t)(row0 + 8) * ldc + col);
                    v0.x += r0.x; v0.y += r0.y; v1.x += r1.x; v1.y += r1.y;
                }
                *(float2*)(C + (size_t)row0 * ldc + col)       = v0;
                *(float2*)(C + (size_t)(row0 + 8) * ldc + col) = v1;
            }
        }
    }
}

// ---------------- weight transpose + bf16 split ------------------------------
__global__ void wsplit_k(const float* __restrict__ W, __nv_bfloat16* __restrict__ Th,
                         __nv_bfloat16* __restrict__ Tl, int Kd, int Nd) {
    __shared__ float t[32][33];
    int n0 = blockIdx.x * 32, k0 = blockIdx.y * 32;
    int tx = threadIdx.x, ty = threadIdx.y;
    #pragma unroll
    for (int i = 0; i < 4; i++)
        t[ty + i * 8][tx] = W[(size_t)(k0 + ty + i * 8) * Nd + n0 + tx];
    __syncthreads();
    #pragma unroll
    for (int i = 0; i < 4; i++) {
        int r = ty + i * 8;
        float v = t[tx][r];
        __nv_bfloat16 hb = __float2bfloat16(v);
        size_t o = (size_t)(n0 + r) * Kd + k0 + tx;
        Th[o] = hb;
        Tl[o] = __float2bfloat16(v - __bfloat162float(hb));
    }
}

// ---------------- rmsnorm -> bf16 split --------------------------------------
__global__ void rmsnorm_k(const float* __restrict__ x, const float* __restrict__ w,
                          __nv_bfloat16* __restrict__ oh, __nv_bfloat16* __restrict__ ol) {
    int row = blockIdx.x;
    const float4* xr = (const float4*)(x + (size_t)row * Dm);
    float4 v = xr[threadIdx.x];
    float ss = v.x*v.x + v.y*v.y + v.z*v.z + v.w*v.w;
    #pragma unroll
    for (int o = 16; o; o >>= 1) ss += __shfl_xor_sync(0xffffffffu, ss, o);
    __shared__ float sws[8];
    int lane = threadIdx.x & 31, wid = threadIdx.x >> 5;
    if (lane == 0) sws[wid] = ss;
    __syncthreads();
    if (threadIdx.x == 0) {
        float t = 0.f;
        #pragma unroll
        for (int i = 0; i < 8; i++) t += sws[i];
        sws[0] = rsqrtf(t * (1.0f / Dm) + 1e-6f);
    }
    __syncthreads();
    float inv = sws[0];
    float4 wv = ((const float4*)w)[threadIdx.x];
    float4 o4;
    o4.x = v.x * inv * wv.x; o4.y = v.y * inv * wv.y;
    o4.z = v.z * inv * wv.z; o4.w = v.w * inv * wv.w;
    __nv_bfloat16 h0 = __float2bfloat16(o4.x), h1 = __float2bfloat16(o4.y);
    __nv_bfloat16 h2 = __float2bfloat16(o4.z), h3 = __float2bfloat16(o4.w);
    __nv_bfloat162 H0; H0.x = h0; H0.y = h1;
    __nv_bfloat162 H1; H1.x = h2; H1.y = h3;
    __nv_bfloat162* ph = (__nv_bfloat162*)(oh + (size_t)row * Dm);
    ph[threadIdx.x * 2]     = H0;
    ph[threadIdx.x * 2 + 1] = H1;
    __nv_bfloat162 L0, L1;
    L0.x = __float2bfloat16(o4.x - __bfloat162float(h0));
    L0.y = __float2bfloat16(o4.y - __bfloat162float(h1));
    L1.x = __float2bfloat16(o4.z - __bfloat162float(h2));
    L1.y = __float2bfloat16(o4.w - __bfloat162float(h3));
    __nv_bfloat162* pl = (__nv_bfloat162*)(ol + (size_t)row * Dm);
    pl[threadIdx.x * 2]     = L0;
    pl[threadIdx.x * 2 + 1] = L1;
}

// ---------------- node/pos + partition starts --------------------------------
__global__ void node_pos_k() {
    int bh = blockIdx.x;
    int b = bh >> 4, h = bh & 15;
    int t = threadIdx.x;
    __shared__ int cnts[256][4];
    __shared__ int base[256][4];
    int myn[8], posl[8];
    int local[4] = {0, 0, 0, 0};
    #pragma unroll
    for (int j = 0; j < 8; j++) {
        int s = t * 8 + j;
        int tok = b * Ss + s;
        const float* lp = g_qkvr + (size_t)tok * NQKV + 3072 + h * 4;
        float l0 = lp[0], l1 = lp[1], l2 = lp[2], l3 = lp[3];
        int n = 0; float bv = l0;
        if (l1 > bv) { bv = l1; n = 1; }
        if (l2 > bv) { bv = l2; n = 2; }
        if (l3 > bv) { bv = l3; n = 3; }
        myn[j] = n;
        posl[j] = local[n];
        local[n]++;
    }
    cnts[t][0] = local[0]; cnts[t][1] = local[1];
    cnts[t][2] = local[2]; cnts[t][3] = local[3];
    __syncthreads();
    if (t == 0) {
        int run[4] = {0, 0, 0, 0};
        for (int i = 0; i < 256; i++)
            #pragma unroll
            for (int v = 0; v < 4; v++) { base[i][v] = run[v]; run[v] += cnts[i][v]; }
        int st = 0;
        #pragma unroll
        for (int v = 0; v < 4; v++) { g_start[bh * 4 + v] = st; st += run[v]; }
    }
    __syncthreads();
    #pragma unroll
    for (int j = 0; j < 8; j++) {
        int s = t * 8 + j;
        int tok = b * Ss + s;
        int n = myn[j];
        g_node[tok * Hh + h] = n;
        g_pos[tok * Hh + h] = (float)(base[t][n] + posl[j]);
    }
}

// ---------------- permute (node partition) + RoPE ----------------------------
__global__ void permute_k() {
    int inst = blockIdx.x * 4 + (threadIdx.x >> 5);   // tok*16 + h
    int lane = threadIdx.x & 31;
    int tok = inst >> 4, h = inst & 15;
    int b = tok >> 11;
    int bh = b * 16 + h;
    int n = g_node[tok * Hh + h];
    float pos = g_pos[tok * Hh + h];
    int startn = g_start[bh * 4 + n];
    int slot = startn + (int)pos;
    const float* src = g_qkvr + (size_t)tok * NQKV;
    float invf = exp2f(-(float)lane * (13.287712379549449f / 32.0f));
    float ang = pos * invf;
    float s, c;
    sincosf(ang, &s, &c);
    size_t drow = ((size_t)bh * Ss + slot) * HDim;
    float q1 = src[h * 64 + lane], q2 = src[h * 64 + lane + 32];
    g_qp[drow + lane]      = q1 * c - q2 * s;
    g_qp[drow + lane + 32] = q2 * c + q1 * s;
    float k1 = src[1024 + h * 64 + lane], k2 = src[1024 + h * 64 + lane + 32];
    g_kp[drow + lane]      = k1 * c - k2 * s;
    g_kp[drow + lane + 32] = k2 * c + k1 * s;
    g_vp[drow + lane]      = src[2048 + h * 64 + lane];
    g_vp[drow + lane + 32] = src[2048 + h * 64 + lane + 32];
    if (lane == 0) {
        g_qstart[bh * Ss + slot] = startn;
        g_orig  [bh * Ss + slot] = tok;
    }
}

// ---------------- attention: dense per-partition causal flash ----------------
#define ATTN_SMEM ((4096 + 4096 + 128 * 65) * 4)
__global__ __launch_bounds__(128)
void attn_k() {
    int bh = blockIdx.y;
    int h = bh & 15;
    int q0 = blockIdx.x * 128;
    int tid = threadIdx.x;
    int j = q0 + tid;                       // slot
    size_t base = (size_t)bh * Ss;
    extern __shared__ float sm[];
    float* Ks = sm;
    float* Vs = sm + 4096;
    float* Sc = sm + 8192;

    float qreg[64];
    const float4* qp = (const float4*)(g_qp + (base + j) * HDim);
    #pragma unroll
    for (int d4 = 0; d4 < 16; d4++) {
        float4 v = qp[d4];
        qreg[d4*4+0] = v.x; qreg[d4*4+1] = v.y; qreg[d4*4+2] = v.z; qreg[d4*4+3] = v.w;
    }
    int startq = g_qstart[base + j];
    int orig   = g_orig[base + j];
    int kt0 = g_qstart[base + q0] >> 6;     // min partition start in this block
    int ktE = (q0 >> 6) + 2;

    float m = -CUDART_INF_F, l = 0.f;
    float acc[64];
    #pragma unroll
    for (int d = 0; d < 64; d++) acc[d] = 0.f;

    for (int kt = kt0; kt < ktE; ++kt) {
        int kb = kt * 64;
        __syncthreads();
        for (int e = tid; e < 1024; e += 128) {
            int r = e >> 4, c = (e & 15) * 4;
            size_t srow = (base + kb + r) * HDim;
            *(float4*)&Ks[r * 64 + c] = *(const float4*)(g_kp + srow + c);
            *(float4*)&Vs[r * 64 + c] = *(const float4*)(g_vp + srow + c);
        }
        __syncthreads();

        float tmax = -CUDART_INF_F;
        #pragma unroll 1
        for (int kk = 0; kk < 64; ++kk) {
            int ki = kb + kk;
            float s = -1e30f;
            if (ki >= startq && ki <= j) {
                float s0 = 0.f, s1 = 0.f, s2 = 0.f, s3 = 0.f;
                const float4* kr = (const float4*)&Ks[kk * 64];
                #pragma unroll
                for (int d4 = 0; d4 < 16; d4++) {
                    float4 kv = kr[d4];
                    s0 = fmaf(qreg[d4*4+0], kv.x, s0);
                    s1 = fmaf(qreg[d4*4+1], kv.y, s1);
                    s2 = fmaf(qreg[d4*4+2], kv.z, s2);
                    s3 = fmaf(qreg[d4*4+3], kv.w, s3);
                }
                s = ((s0 + s1) + (s2 + s3)) * 0.125f;
            }
            Sc[tid * 65 + kk] = s;
            tmax = fmaxf(tmax, s);
        }
        if (tmax > -1e29f) {
            float nm = fmaxf(m, tmax);
            float scl = fexp(m - nm);
            l *= scl;
            #pragma unroll
            for (int d = 0; d < 64; d++) acc[d] *= scl;
            #pragma unroll 1
            for (int kk = 0; kk < 64; ++kk) {
                float p = fexp(Sc[tid * 65 + kk] - nm);
                l += p;
                const float4* vr = (const float4*)&Vs[kk * 64];
                #pragma unroll
                for (int d4 = 0; d4 < 16; d4++) {
                    float4 vv = vr[d4];
                    acc[d4*4+0] = fmaf(p, vv.x, acc[d4*4+0]);
                    acc[d4*4+1] = fmaf(p, vv.y, acc[d4*4+1]);
                    acc[d4*4+2] = fmaf(p, vv.z, acc[d4*4+2]);
                    acc[d4*4+3] = fmaf(p, vv.w, acc[d4*4+3]);
                }
            }
            m = nm;
        }
    }
    float inv = 1.f / l;
    __nv_bfloat162* oh = (__nv_bfloat162*)(g_cxh + (size_t)orig * Dm + h * HDim);
    __nv_bfloat162* ol = (__nv_bfloat162*)(g_cxl + (size_t)orig * Dm + h * HDim);
    #pragma unroll
    for (int d2 = 0; d2 < 32; d2++) {
        float v0 = acc[d2*2] * inv, v1 = acc[d2*2+1] * inv;
        __nv_bfloat16 h0 = __float2bfloat16(v0), h1 = __float2bfloat16(v1);
        __nv_bfloat162 H; H.x = h0; H.y = h1;
        oh[d2] = H;
        __nv_bfloat162 L;
        L.x = __float2bfloat16(v0 - __bfloat162float(h0));
        L.y = __float2bfloat16(v1 - __bfloat162float(h1));
        ol[d2] = L;
    }
}

// ---------------- SwiGLU elementwise -> bf16 split ---------------------------
__global__ void silu_mul_k() {
    size_t i = (size_t)blockIdx.x * 256 + threadIdx.x;   // float4 idx over TOK*Ff/4
    size_t t = i >> 10;                                   // row (1024 float4 per row)
    size_t c4 = i & 1023;
    float4 a = ((const float4*)(g_a12 + t * 2 * Ff))[c4];
    float4 c = ((const float4*)(g_a12 + t * 2 * Ff + Ff))[c4];
    float r0 = a.x / (1.f + fexp(-a.x)) * c.x;
    float r1 = a.y / (1.f + fexp(-a.y)) * c.y;
    float r2 = a.z / (1.f + fexp(-a.z)) * c.z;
    float r3 = a.w / (1.f + fexp(-a.w)) * c.w;
    __nv_bfloat16 h0 = __float2bfloat16(r0), h1 = __float2bfloat16(r1);
    __nv_bfloat16 h2 = __float2bfloat16(r2), h3 = __float2bfloat16(r3);
    __nv_bfloat162 H0; H0.x = h0; H0.y = h1;
    __nv_bfloat162 H1; H1.x = h2; H1.y = h3;
    ((__nv_bfloat162*)g_s1h)[i*2]   = H0;
    ((__nv_bfloat162*)g_s1h)[i*2+1] = H1;
    __nv_bfloat162 L0, L1;
    L0.x = __float2bfloat16(r0 - __bfloat162float(h0));
    L0.y = __float2bfloat16(r1 - __bfloat162float(h1));
    L1.x = __float2bfloat16(r2 - __bfloat162float(h2));
    L1.y = __float2bfloat16(r3 - __bfloat162float(h3));
    ((__nv_bfloat162*)g_s1l)[i*2]   = L0;
    ((__nv_bfloat162*)g_s1l)[i*2+1] = L1;
}

// ---------------- host launcher ----------------------------------------------
#define SYM(p, s) do { void* _t; cudaGetSymbolAddress(&_t, s); p = (decltype(p))_t; } while (0)

extern "C" void kernel_launch(void* const* d_in, const int* in_sizes, int n_in,
                              void* d_out, int out_size) {
    const float* x      = (const float*)d_in[0];
    const float* attn_w = (const float*)d_in[1];
    const float* ffn_w  = (const float*)d_in[2];
    const float* Wq     = (const float*)d_in[3];
    const float* Wk     = (const float*)d_in[4];
    const float* Wv     = (const float*)d_in[5];
    const float* Wo     = (const float*)d_in[6];
    const float* Wr     = (const float*)d_in[7];
    const float* w1     = (const float*)d_in[8];
    const float* w2     = (const float*)d_in[9];
    const float* w3     = (const float*)d_in[10];
    float* out = (float*)d_out;

    float *p_qkvr, *p_x2, *p_a12;
    SYM(p_qkvr, g_qkvr); SYM(p_x2, g_x2); SYM(p_a12, g_a12);
    __nv_bfloat16 *p_hh, *p_hl, *p_cxh, *p_cxl, *p_s1h, *p_s1l;
    SYM(p_hh, g_hh); SYM(p_hl, g_hl); SYM(p_cxh, g_cxh); SYM(p_cxl, g_cxl);
    SYM(p_s1h, g_s1h); SYM(p_s1l, g_s1l);
    __nv_bfloat16 *wAh, *wAl, *woh, *wol, *w12h, *w12l, *w3h, *w3l;
    SYM(wAh, g_wAh); SYM(wAl, g_wAl); SYM(woh, g_woh); SYM(wol, g_wol);
    SYM(w12h, g_w12h); SYM(w12l, g_w12l); SYM(w3h, g_w3h); SYM(w3l, g_w3l);

    cudaFuncSetAttribute(attn_k, cudaFuncAttributeMaxDynamicSharedMemorySize, ATTN_SMEM);
    cudaFuncSetAttribute(gemm_hmma, cudaFuncAttributeMaxDynamicSharedMemorySize, GH_SMEM);

    // zero pad rows [3136, 3200) of fused A-weights
    cudaMemsetAsync(wAh + (size_t)3136 * Dm, 0, 64 * Dm * sizeof(__nv_bfloat16));
    cudaMemsetAsync(wAl + (size_t)3136 * Dm, 0, 64 * Dm * sizeof(__nv_bfloat16));

    dim3 tb(32, 8);
    wsplit_k<<<dim3(Dm/32, Dm/32), tb>>>(Wq, wAh,               wAl,               Dm, Dm);
    wsplit_k<<<dim3(Dm/32, Dm/32), tb>>>(Wk, wAh + 1024*Dm,     wAl + 1024*Dm,     Dm, Dm);
    wsplit_k<<<dim3(Dm/32, Dm/32), tb>>>(Wv, wAh + 2048*Dm,     wAl + 2048*Dm,     Dm, Dm);
    wsplit_k<<<dim3(2,     Dm/32), tb>>>(Wr, wAh + 3072*Dm,     wAl + 3072*Dm,     Dm, 64);
    wsplit_k<<<dim3(Dm/32, Dm/32), tb>>>(Wo, woh, wol, Dm, Dm);
    wsplit_k<<<dim3(Ff/32, Dm/32), tb>>>(w1, w12h,              w12l,              Dm, Ff);
    wsplit_k<<<dim3(Ff/32, Dm/32), tb>>>(w2, w12h + (size_t)Ff*Dm, w12l + (size_t)Ff*Dm, Dm, Ff);
    wsplit_k<<<dim3(Dm/32, Ff/32), tb>>>(w3, w3h, w3l, Ff, Dm);

    // 1. h = rmsnorm(x) -> bf16 split
    rmsnorm_k<<<TOK, 256>>>(x, attn_w, p_hh, p_hl);

    // 2. fused q|k|v|router GEMM
    gemm_hmma<<<dim3(NQKV/128, TOK/128), 256, GH_SMEM>>>(
        p_hh, p_hl, wAh, wAl, nullptr, p_qkvr, TOK, NQKV, NQKV, Dm);

    // 3. node/pos + partition & rope
    node_pos_k<<<32, 256>>>();
    permute_k<<<TOK * Hh / 4, 128>>>();

    // 4. partitioned causal flash attention -> ctx (bf16 split)
    attn_k<<<dim3(Ss / 128, 2 * Hh), 128, ATTN_SMEM>>>();

    // 5. x2 = x + ctx @ Wo
    dim3 gq(Dm / 128, TOK / 128);
    gemm_hmma<<<gq, 256, GH_SMEM>>>(p_cxh, p_cxl, woh, wol, x, p_x2, TOK, Dm, Dm, Dm);

    // 6. h2 = rmsnorm(x2) -> bf16 split
    rmsnorm_k<<<TOK, 256>>>(p_x2, ffn_w, p_hh, p_hl);

    // 7. fused w1|w2 GEMM + SwiGLU
    gemm_hmma<<<dim3(2*Ff/128, TOK/128), 256, GH_SMEM>>>(
        p_hh, p_hl, w12h, w12l, nullptr, p_a12, TOK, 2*Ff, 2*Ff, Dm);
    silu_mul_k<<<TOK * Ff / 4 / 256, 256>>>();

    // 8. out = x2 + (silu(a1)*a2) @ w3
    gemm_hmma<<<gq, 256, GH_SMEM>>>(p_s1h, p_s1l, w3h, w3l, p_x2, out, TOK, Dm, Dm, Ff);
}

// round 5
// speedup vs baseline: 2.6880x; 1.0655x over previous
#include <cuda_runtime.h>
#include <cuda_bf16.h>
#include <math.h>
#include <math_constants.h>
#include <stdint.h>

#define TOK 4096   // B*S
#define Dm  1024
#define Hh  16
#define HDim 64
#define Ff  4096
#define Ss  2048
#define NQKV 3200  // q(1024) k(1024) v(1024) router(64) pad(64)

// ---------------- fp32 scratch ----------------------------------------------
__device__ float g_qkvr[TOK*NQKV];
__device__ float g_x2 [TOK*Dm];
__device__ int   g_node[TOK*Hh];
__device__ float g_pos [TOK*Hh];
__device__ int   g_start [32*4];
__device__ int   g_qstart[32*Ss];
__device__ int   g_orig  [32*Ss];
__device__ float g_qp[32*Ss*HDim];
__device__ float g_kp[32*Ss*HDim];
__device__ float g_vp[32*Ss*HDim];

// ---------------- bf16 split activations ------------------------------------
__device__ __nv_bfloat16 g_hh [TOK*Dm], g_hl [TOK*Dm];
__device__ __nv_bfloat16 g_cxh[TOK*Dm], g_cxl[TOK*Dm];
__device__ __nv_bfloat16 g_s1h[TOK*Ff], g_s1l[TOK*Ff];

// ---------------- bf16 split transposed weights [N,K] -----------------------
__device__ __nv_bfloat16 g_wAh[NQKV*Dm], g_wAl[NQKV*Dm];    // Wq|Wk|Wv|Wr|0
__device__ __nv_bfloat16 g_woh[Dm*Dm],   g_wol[Dm*Dm];
__device__ __nv_bfloat16 g_w12h[2*Ff*Dm], g_w12l[2*Ff*Dm];  // w1/w2 interleaved by 64-col group
__device__ __nv_bfloat16 g_w3h[Dm*Ff],   g_w3l[Dm*Ff];

// ---------------- helpers -----------------------------------------------------
__device__ __forceinline__ uint32_t s2u(const void* p) {
    uint32_t a;
    asm("{ .reg .u64 t; cvta.to.shared.u64 t, %1; cvt.u32.u64 %0, t; }" : "=r"(a) : "l"(p));
    return a;
}

#define LDSM4(r, addr) \
    asm volatile("ldmatrix.sync.aligned.m8n8.x4.shared.b16 {%0,%1,%2,%3}, [%4];" \
        : "=r"((r)[0]), "=r"((r)[1]), "=r"((r)[2]), "=r"((r)[3]) : "r"(addr))

#define MMA(d, a, b) \
    asm volatile("mma.sync.aligned.m16n8k16.row.col.f32.bf16.bf16.f32 " \
        "{%0,%1,%2,%3}, {%4,%5,%6,%7}, {%8,%9}, {%0,%1,%2,%3};" \
        : "+f"((d)[0]), "+f"((d)[1]), "+f"((d)[2]), "+f"((d)[3]) \
        : "r"((a)[0]), "r"((a)[1]), "r"((a)[2]), "r"((a)[3]), "r"((b)[0]), "r"((b)[1]))

#define CPASYNC(dst, src) \
    asm volatile("cp.async.cg.shared.global [%0], [%1], 16;" :: "r"(dst), "l"(src))

// ---------------- fast exp (FMA pipe only) ----------------------------------
__device__ __forceinline__ float fexp(float x) {
    x = fminf(fmaxf(x, -87.0f), 88.0f);
    float y = x * 1.4426950408889634f;
    float n = rintf(y);
    float f = y - n;
    float p = 1.3333558146e-3f;
    p = fmaf(p, f, 9.6181291076e-3f);
    p = fmaf(p, f, 5.5504108665e-2f);
    p = fmaf(p, f, 2.4022650696e-1f);
    p = fmaf(p, f, 6.9314718056e-1f);
    p = fmaf(p, f, 1.0f);
    return p * __int_as_float(((int)n + 127) << 23);
}

// ---------------- HMMA split-bf16 GEMM, 2-stage, 2 CTAs/SM -------------------
// swiglu==0: C[M,Nc](ldc) = A@B^T (+R)
// swiglu==1: tile = one 64-col group g=blockIdx.x of interleaved w1|w2;
//            writes silu(a1)*a2 (bf16 split) to Oh/Ol[M,Ff] at cols g*64..g*64+63
#define BUF_BYTES 40960
#define GH_SMEM   (2 * BUF_BYTES)

__global__ __launch_bounds__(256, 2)
void gemm_hmma(const __nv_bfloat16* __restrict__ Ah, const __nv_bfloat16* __restrict__ Al,
               const __nv_bfloat16* __restrict__ Bh, const __nv_bfloat16* __restrict__ Bl,
               const float* __restrict__ R, float* __restrict__ C,
               int M, int Nc, int ldc, int K,
               __nv_bfloat16* __restrict__ Oh, __nv_bfloat16* __restrict__ Ol, int swiglu) {
    extern __shared__ char smraw[];
    const int tid  = threadIdx.x;
    const int lane = tid & 31, wid = tid >> 5;
    const int m0 = blockIdx.y * 128, n0 = blockIdx.x * 128;
    const int warp_m = (wid >> 2) * 64, warp_n = (wid & 3) * 32;
    const int nc = K >> 5;
    const uint32_t sb = s2u(smraw);

    const char* gA  = (const char*)Ah + (size_t)m0 * K * 2;
    const char* gAl = (const char*)Al + (size_t)m0 * K * 2;
    const char* gB  = (const char*)Bh + (size_t)n0 * K * 2;
    const char* gBl = (const char*)Bl + (size_t)n0 * K * 2;

    int lr0 = tid >> 2,          lc0 = (tid & 3) * 16;
    int lr1 = (tid + 256) >> 2,  lc1 = lc0;

    #define ISSUE(buf, kc) do { \
        uint32_t db = sb + (buf) * BUF_BYTES; \
        size_t ko = (size_t)(kc) * 64; \
        uint32_t so0 = lr0 * 80 + lc0, so1 = lr1 * 80 + lc1; \
        size_t go0 = (size_t)lr0 * (K * 2) + ko + lc0; \
        size_t go1 = (size_t)lr1 * (K * 2) + ko + lc1; \
        CPASYNC(db + so0,         gA  + go0); CPASYNC(db + so1,         gA  + go1); \
        CPASYNC(db + 10240 + so0, gAl + go0); CPASYNC(db + 10240 + so1, gAl + go1); \
        CPASYNC(db + 20480 + so0, gB  + go0); CPASYNC(db + 20480 + so1, gB  + go1); \
        CPASYNC(db + 30720 + so0, gBl + go0); CPASYNC(db + 30720 + so1, gBl + go1); \
        asm volatile("cp.async.commit_group;"); \
    } while (0)

    ISSUE(0, 0);
    ISSUE(1, 1);

    float acc[4][4][4];
    #pragma unroll
    for (int i = 0; i < 4; i++)
        #pragma unroll
        for (int j = 0; j < 4; j++)
            #pragma unroll
            for (int q = 0; q < 4; q++) acc[i][j][q] = 0.f;

    const int a_row = (lane & 7) + ((lane >> 3) & 1) * 8;
    const int a_cb  = (lane >> 4) * 16;
    const int b_row = (lane & 7) + (lane >> 4) * 8;
    const int b_cb  = ((lane >> 3) & 1) * 16;

    #pragma unroll 1
    for (int kc = 0; kc < nc; kc++) {
        if (kc + 1 < nc) asm volatile("cp.async.wait_group 1;");
        else             asm volatile("cp.async.wait_group 0;");
        __syncthreads();
        uint32_t db = sb + (kc & 1) * BUF_BYTES;
        #pragma unroll
        for (int ks = 0; ks < 2; ks++) {
            uint32_t ah[4][4], al[4][4], bh[4][2], bl[4][2];
            #pragma unroll
            for (int mt = 0; mt < 4; mt++) {
                uint32_t ad = db + (warp_m + mt * 16 + a_row) * 80 + a_cb + ks * 32;
                LDSM4(ah[mt], ad);
                LDSM4(al[mt], ad + 10240);
            }
            #pragma unroll
            for (int p = 0; p < 2; p++) {
                uint32_t bd = db + 20480 + (warp_n + p * 16 + b_row) * 80 + b_cb + ks * 32;
                LDSM4(&bh[2 * p][0], bd);
                LDSM4(&bl[2 * p][0], bd + 10240);
            }
            #pragma unroll
            for (int mt = 0; mt < 4; mt++)
                #pragma unroll
                for (int nt = 0; nt < 4; nt++) MMA(acc[mt][nt], ah[mt], bh[nt]);
            #pragma unroll
            for (int mt = 0; mt < 4; mt++)
                #pragma unroll
                for (int nt = 0; nt < 4; nt++) MMA(acc[mt][nt], ah[mt], bl[nt]);
            #pragma unroll
            for (int mt = 0; mt < 4; mt++)
                #pragma unroll
                for (int nt = 0; nt < 4; nt++) MMA(acc[mt][nt], al[mt], bh[nt]);
        }
        __syncthreads();
        if (kc + 2 < nc) ISSUE(kc & 1, kc + 2);
    }
    #undef ISSUE

    const int g  = lane >> 2;
    const int cc = (lane & 3) * 2;

    if (swiglu) {
        // tile cols [0,64) = w1 group, [64,128) = w2 group (same output cols)
        float* sm2 = (float*)smraw;          // [128][68] fp32 staging for a2
        if ((wid & 3) >= 2) {
            #pragma unroll
            for (int mt = 0; mt < 4; mt++) {
                int row0 = warp_m + mt * 16 + g;
                #pragma unroll
                for (int nt = 0; nt < 4; nt++) {
                    int c = warp_n - 64 + nt * 8 + cc;
                    sm2[row0 * 68 + c]           = acc[mt][nt][0];
                    sm2[row0 * 68 + c + 1]       = acc[mt][nt][1];
                    sm2[(row0 + 8) * 68 + c]     = acc[mt][nt][2];
                    sm2[(row0 + 8) * 68 + c + 1] = acc[mt][nt][3];
                }
            }
        }
        __syncthreads();
        if ((wid & 3) < 2) {
            size_t colbase = (size_t)blockIdx.x * 64;
            #pragma unroll
            for (int mt = 0; mt < 4; mt++) {
                #pragma unroll
                for (int rr = 0; rr < 2; rr++) {
                    int row = warp_m + mt * 16 + g + rr * 8;
                    size_t orow = (size_t)(m0 + row) * Ff + colbase;
                    #pragma unroll
                    for (int nt = 0; nt < 4; nt++) {
                        int c = warp_n + nt * 8 + cc;
                        float a1a = acc[mt][nt][rr * 2], a1b = acc[mt][nt][rr * 2 + 1];
                        float a2a = sm2[row * 68 + c], a2b = sm2[row * 68 + c + 1];
                        float r0 = a1a / (1.f + fexp(-a1a)) * a2a;
                        float r1 = a1b / (1.f + fexp(-a1b)) * a2b;
                        __nv_bfloat16 h0 = __float2bfloat16(r0), h1 = __float2bfloat16(r1);
                        __nv_bfloat162 H; H.x = h0; H.y = h1;
                        *(__nv_bfloat162*)(Oh + orow + c) = H;
                        __nv_bfloat162 L;
                        L.x = __float2bfloat16(r0 - __bfloat162float(h0));
                        L.y = __float2bfloat16(r1 - __bfloat162float(h1));
                        *(__nv_bfloat162*)(Ol + orow + c) = L;
                    }
                }
            }
        }
        return;
    }

    #pragma unroll
    for (int mt = 0; mt < 4; mt++) {
        int row0 = m0 + warp_m + mt * 16 + g;
        #pragma unroll
        for (int nt = 0; nt < 4; nt++) {
            int col = n0 + warp_n + nt * 8 + cc;
            if (col < Nc) {
                float2 v0 = make_float2(acc[mt][nt][0], acc[mt][nt][1]);
                float2 v1 = make_float2(acc[mt][nt][2], acc[mt][nt][3]);
                if (R) {
                    float2 r0 = *(const float2*)(R + (size_t)row0 * ldc + col);
                    float2 r1 = *(const float2*)(R + (size_t)(row0 + 8) * ldc + col);
                    v0.x += r0.x; v0.y += r0.y; v1.x += r1.x; v1.y += r1.y;
                }
                *(float2*)(C + (size_t)row0 * ldc + col)       = v0;
                *(float2*)(C + (size_t)(row0 + 8) * ldc + col) = v1;
            }
        }
    }
}

// ---------------- weight transpose + bf16 split (+ optional row remap) -------
// mode 0: row n -> n ; mode 1 (w1): n -> (n>>6)*128 + (n&63)
// mode 2 (w2): n -> (n>>6)*128 + 64 + (n&63)
__global__ void wsplit_k(const float* __restrict__ W, __nv_bfloat16* __restrict__ Th,
                         __nv_bfloat16* __restrict__ Tl, int Kd, int Nd, int mode) {
    __shared__ float t[32][33];
    int n0 = blockIdx.x * 32, k0 = blockIdx.y * 32;
    int tx = threadIdx.x, ty = threadIdx.y;
    #pragma unroll
    for (int i = 0; i < 4; i++)
        t[ty + i * 8][tx] = W[(size_t)(k0 + ty + i * 8) * Nd + n0 + tx];
    __syncthreads();
    #pragma unroll
    for (int i = 0; i < 4; i++) {
        int r = ty + i * 8;
        int n = n0 + r;
        size_t orow = (mode == 0) ? (size_t)n
                    : (size_t)((n >> 6) * 128 + (n & 63) + ((mode == 2) ? 64 : 0));
        float v = t[tx][r];
        __nv_bfloat16 hb = __float2bfloat16(v);
        size_t o = orow * Kd + k0 + tx;
        Th[o] = hb;
        Tl[o] = __float2bfloat16(v - __bfloat162float(hb));
    }
}

// ---------------- rmsnorm -> bf16 split --------------------------------------
__global__ void rmsnorm_k(const float* __restrict__ x, const float* __restrict__ w,
                          __nv_bfloat16* __restrict__ oh, __nv_bfloat16* __restrict__ ol) {
    int row = blockIdx.x;
    const float4* xr = (const float4*)(x + (size_t)row * Dm);
    float4 v = xr[threadIdx.x];
    float ss = v.x*v.x + v.y*v.y + v.z*v.z + v.w*v.w;
    #pragma unroll
    for (int o = 16; o; o >>= 1) ss += __shfl_xor_sync(0xffffffffu, ss, o);
    __shared__ float sws[8];
    int lane = threadIdx.x & 31, wid = threadIdx.x >> 5;
    if (lane == 0) sws[wid] = ss;
    __syncthreads();
    if (threadIdx.x == 0) {
        float t = 0.f;
        #pragma unroll
        for (int i = 0; i < 8; i++) t += sws[i];
        sws[0] = rsqrtf(t * (1.0f / Dm) + 1e-6f);
    }
    __syncthreads();
    float inv = sws[0];
    float4 wv = ((const float4*)w)[threadIdx.x];
    float4 o4;
    o4.x = v.x * inv * wv.x; o4.y = v.y * inv * wv.y;
    o4.z = v.z * inv * wv.z; o4.w = v.w * inv * wv.w;
    __nv_bfloat16 h0 = __float2bfloat16(o4.x), h1 = __float2bfloat16(o4.y);
    __nv_bfloat16 h2 = __float2bfloat16(o4.z), h3 = __float2bfloat16(o4.w);
    __nv_bfloat162 H0; H0.x = h0; H0.y = h1;
    __nv_bfloat162 H1; H1.x = h2; H1.y = h3;
    __nv_bfloat162* ph = (__nv_bfloat162*)(oh + (size_t)row * Dm);
    ph[threadIdx.x * 2]     = H0;
    ph[threadIdx.x * 2 + 1] = H1;
    __nv_bfloat162 L0, L1;
    L0.x = __float2bfloat16(o4.x - __bfloat162float(h0));
    L0.y = __float2bfloat16(o4.y - __bfloat162float(h1));
    L1.x = __float2bfloat16(o4.z - __bfloat162float(h2));
    L1.y = __float2bfloat16(o4.w - __bfloat162float(h3));
    __nv_bfloat162* pl = (__nv_bfloat162*)(ol + (size_t)row * Dm);
    pl[threadIdx.x * 2]     = L0;
    pl[threadIdx.x * 2 + 1] = L1;
}

// ---------------- node/pos + partition starts --------------------------------
__global__ void node_pos_k() {
    int bh = blockIdx.x;
    int b = bh >> 4, h = bh & 15;
    int t = threadIdx.x;
    __shared__ int cnts[256][4];
    __shared__ int base[256][4];
    int myn[8], posl[8];
    int local[4] = {0, 0, 0, 0};
    #pragma unroll
    for (int j = 0; j < 8; j++) {
        int s = t * 8 + j;
        int tok = b * Ss + s;
        const float* lp = g_qkvr + (size_t)tok * NQKV + 3072 + h * 4;
        float l0 = lp[0], l1 = lp[1], l2 = lp[2], l3 = lp[3];
        int n = 0; float bv = l0;
        if (l1 > bv) { bv = l1; n = 1; }
        if (l2 > bv) { bv = l2; n = 2; }
        if (l3 > bv) { bv = l3; n = 3; }
        myn[j] = n;
        posl[j] = local[n];
        local[n]++;
    }
    cnts[t][0] = local[0]; cnts[t][1] = local[1];
    cnts[t][2] = local[2]; cnts[t][3] = local[3];
    __syncthreads();
    if (t == 0) {
        int run[4] = {0, 0, 0, 0};
        for (int i = 0; i < 256; i++)
            #pragma unroll
            for (int v = 0; v < 4; v++) { base[i][v] = run[v]; run[v] += cnts[i][v]; }
        int st = 0;
        #pragma unroll
        for (int v = 0; v < 4; v++) { g_start[bh * 4 + v] = st; st += run[v]; }
    }
    __syncthreads();
    #pragma unroll
    for (int j = 0; j < 8; j++) {
        int s = t * 8 + j;
        int tok = b * Ss + s;
        int n = myn[j];
        g_node[tok * Hh + h] = n;
        g_pos[tok * Hh + h] = (float)(base[t][n] + posl[j]);
    }
}

// ---------------- permute (node partition) + RoPE ----------------------------
__global__ void permute_k() {
    int inst = blockIdx.x * 4 + (threadIdx.x >> 5);   // tok*16 + h
    int lane = threadIdx.x & 31;
    int tok = inst >> 4, h = inst & 15;
    int b = tok >> 11;
    int bh = b * 16 + h;
    int n = g_node[tok * Hh + h];
    float pos = g_pos[tok * Hh + h];
    int startn = g_start[bh * 4 + n];
    int slot = startn + (int)pos;
    const float* src = g_qkvr + (size_t)tok * NQKV;
    float invf = exp2f(-(float)lane * (13.287712379549449f / 32.0f));
    float ang = pos * invf;
    float s, c;
    sincosf(ang, &s, &c);
    size_t drow = ((size_t)bh * Ss + slot) * HDim;
    float q1 = src[h * 64 + lane], q2 = src[h * 64 + lane + 32];
    g_qp[drow + lane]      = q1 * c - q2 * s;
    g_qp[drow + lane + 32] = q2 * c + q1 * s;
    float k1 = src[1024 + h * 64 + lane], k2 = src[1024 + h * 64 + lane + 32];
    g_kp[drow + lane]      = k1 * c - k2 * s;
    g_kp[drow + lane + 32] = k2 * c + k1 * s;
    g_vp[drow + lane]      = src[2048 + h * 64 + lane];
    g_vp[drow + lane + 32] = src[2048 + h * 64 + lane + 32];
    if (lane == 0) {
        g_qstart[bh * Ss + slot] = startn;
        g_orig  [bh * Ss + slot] = tok;
    }
}

// ---------------- attention: dense per-partition causal flash ----------------
#define ATTN_SMEM ((4096 + 4096 + 128 * 65) * 4)
__global__ __launch_bounds__(128)
void attn_k() {
    int bh = blockIdx.y;
    int h = bh & 15;
    int q0 = blockIdx.x * 128;
    int tid = threadIdx.x;
    int j = q0 + tid;                       // slot
    size_t base = (size_t)bh * Ss;
    extern __shared__ float sm[];
    float* Ks = sm;
    float* Vs = sm + 4096;
    float* Sc = sm + 8192;

    float qreg[64];
    const float4* qp = (const float4*)(g_qp + (base + j) * HDim);
    #pragma unroll
    for (int d4 = 0; d4 < 16; d4++) {
        float4 v = qp[d4];
        qreg[d4*4+0] = v.x; qreg[d4*4+1] = v.y; qreg[d4*4+2] = v.z; qreg[d4*4+3] = v.w;
    }
    int startq = g_qstart[base + j];
    int orig   = g_orig[base + j];
    int kt0 = g_qstart[base + q0] >> 6;
    int ktE = (q0 >> 6) + 2;

    float m = -CUDART_INF_F, l = 0.f;
    float acc[64];
    #pragma unroll
    for (int d = 0; d < 64; d++) acc[d] = 0.f;

    for (int kt = kt0; kt < ktE; ++kt) {
        int kb = kt * 64;
        __syncthreads();
        for (int e = tid; e < 1024; e += 128) {
            int r = e >> 4, c = (e & 15) * 4;
            size_t srow = (base + kb + r) * HDim;
            *(float4*)&Ks[r * 64 + c] = *(const float4*)(g_kp + srow + c);
            *(float4*)&Vs[r * 64 + c] = *(const float4*)(g_vp + srow + c);
        }
        __syncthreads();

        float tmax = -CUDART_INF_F;
        #pragma unroll 1
        for (int kk = 0; kk < 64; ++kk) {
            int ki = kb + kk;
            float s = -1e30f;
            if (ki >= startq && ki <= j) {
                float s0 = 0.f, s1 = 0.f, s2 = 0.f, s3 = 0.f;
                const float4* kr = (const float4*)&Ks[kk * 64];
                #pragma unroll
                for (int d4 = 0; d4 < 16; d4++) {
                    float4 kv = kr[d4];
                    s0 = fmaf(qreg[d4*4+0], kv.x, s0);
                    s1 = fmaf(qreg[d4*4+1], kv.y, s1);
                    s2 = fmaf(qreg[d4*4+2], kv.z, s2);
                    s3 = fmaf(qreg[d4*4+3], kv.w, s3);
                }
                s = ((s0 + s1) + (s2 + s3)) * 0.125f;
            }
            Sc[tid * 65 + kk] = s;
            tmax = fmaxf(tmax, s);
        }
        if (tmax > -1e29f) {
            float nm = fmaxf(m, tmax);
            float scl = fexp(m - nm);
            l *= scl;
            #pragma unroll
            for (int d = 0; d < 64; d++) acc[d] *= scl;
            #pragma unroll 1
            for (int kk = 0; kk < 64; ++kk) {
                float p = fexp(Sc[tid * 65 + kk] - nm);
                l += p;
                const float4* vr = (const float4*)&Vs[kk * 64];
                #pragma unroll
                for (int d4 = 0; d4 < 16; d4++) {
                    float4 vv = vr[d4];
                    acc[d4*4+0] = fmaf(p, vv.x, acc[d4*4+0]);
                    acc[d4*4+1] = fmaf(p, vv.y, acc[d4*4+1]);
                    acc[d4*4+2] = fmaf(p, vv.z, acc[d4*4+2]);
                    acc[d4*4+3] = fmaf(p, vv.w, acc[d4*4+3]);
                }
            }
            m = nm;
        }
    }
    float inv = 1.f / l;
    __nv_bfloat162* oh = (__nv_bfloat162*)(g_cxh + (size_t)orig * Dm + h * HDim);
    __nv_bfloat162* ol = (__nv_bfloat162*)(g_cxl + (size_t)orig * Dm + h * HDim);
    #pragma unroll
    for (int d2 = 0; d2 < 32; d2++) {
        float v0 = acc[d2*2] * inv, v1 = acc[d2*2+1] * inv;
        __nv_bfloat16 h0 = __float2bfloat16(v0), h1 = __float2bfloat16(v1);
        __nv_bfloat162 H; H.x = h0; H.y = h1;
        oh[d2] = H;
        __nv_bfloat162 L;
        L.x = __float2bfloat16(v0 - __bfloat162float(h0));
        L.y = __float2bfloat16(v1 - __bfloat162float(h1));
        ol[d2] = L;
    }
}

// ---------------- host launcher ----------------------------------------------
#define SYM(p, s) do { void* _t; cudaGetSymbolAddress(&_t, s); p = (decltype(p))_t; } while (0)

extern "C" void kernel_launch(void* const* d_in, const int* in_sizes, int n_in,
                              void* d_out, int out_size) {
    const float* x      = (const float*)d_in[0];
    const float* attn_w = (const float*)d_in[1];
    const float* ffn_w  = (const float*)d_in[2];
    const float* Wq     = (const float*)d_in[3];
    const float* Wk     = (const float*)d_in[4];
    const float* Wv     = (const float*)d_in[5];
    const float* Wo     = (const float*)d_in[6];
    const float* Wr     = (const float*)d_in[7];
    const float* w1     = (const float*)d_in[8];
    const float* w2     = (const float*)d_in[9];
    const float* w3     = (const float*)d_in[10];
    float* out = (float*)d_out;

    float *p_qkvr, *p_x2;
    SYM(p_qkvr, g_qkvr); SYM(p_x2, g_x2);
    __nv_bfloat16 *p_hh, *p_hl, *p_cxh, *p_cxl, *p_s1h, *p_s1l;
    SYM(p_hh, g_hh); SYM(p_hl, g_hl); SYM(p_cxh, g_cxh); SYM(p_cxl, g_cxl);
    SYM(p_s1h, g_s1h); SYM(p_s1l, g_s1l);
    __nv_bfloat16 *wAh, *wAl, *woh, *wol, *w12h, *w12l, *w3h, *w3l;
    SYM(wAh, g_wAh); SYM(wAl, g_wAl); SYM(woh, g_woh); SYM(wol, g_wol);
    SYM(w12h, g_w12h); SYM(w12l, g_w12l); SYM(w3h, g_w3h); SYM(w3l, g_w3l);

    cudaFuncSetAttribute(attn_k, cudaFuncAttributeMaxDynamicSharedMemorySize, ATTN_SMEM);
    cudaFuncSetAttribute(gemm_hmma, cudaFuncAttributeMaxDynamicSharedMemorySize, GH_SMEM);

    // zero pad rows [3136, 3200) of fused A-weights
    cudaMemsetAsync(wAh + (size_t)3136 * Dm, 0, 64 * Dm * sizeof(__nv_bfloat16));
    cudaMemsetAsync(wAl + (size_t)3136 * Dm, 0, 64 * Dm * sizeof(__nv_bfloat16));

    dim3 tb(32, 8);
    wsplit_k<<<dim3(Dm/32, Dm/32), tb>>>(Wq, wAh,           wAl,           Dm, Dm, 0);
    wsplit_k<<<dim3(Dm/32, Dm/32), tb>>>(Wk, wAh + 1024*Dm, wAl + 1024*Dm, Dm, Dm, 0);
    wsplit_k<<<dim3(Dm/32, Dm/32), tb>>>(Wv, wAh + 2048*Dm, wAl + 2048*Dm, Dm, Dm, 0);
    wsplit_k<<<dim3(2,     Dm/32), tb>>>(Wr, wAh + 3072*Dm, wAl + 3072*Dm, Dm, 64, 0);
    wsplit_k<<<dim3(Dm/32, Dm/32), tb>>>(Wo, woh, wol, Dm, Dm, 0);
    wsplit_k<<<dim3(Ff/32, Dm/32), tb>>>(w1, w12h, w12l, Dm, Ff, 1);
    wsplit_k<<<dim3(Ff/32, Dm/32), tb>>>(w2, w12h, w12l, Dm, Ff, 2);
    wsplit_k<<<dim3(Dm/32, Ff/32), tb>>>(w3, w3h, w3l, Ff, Dm, 0);

    // 1. h = rmsnorm(x) -> bf16 split
    rmsnorm_k<<<TOK, 256>>>(x, attn_w, p_hh, p_hl);

    // 2. fused q|k|v|router GEMM
    gemm_hmma<<<dim3(NQKV/128, TOK/128), 256, GH_SMEM>>>(
        p_hh, p_hl, wAh, wAl, nullptr, p_qkvr, TOK, NQKV, NQKV, Dm,
        nullptr, nullptr, 0);

    // 3. node/pos + partition & rope
    node_pos_k<<<32, 256>>>();
    permute_k<<<TOK * Hh / 4, 128>>>();

    // 4. partitioned causal flash attention -> ctx (bf16 split)
    attn_k<<<dim3(Ss / 128, 2 * Hh), 128, ATTN_SMEM>>>();

    // 5. x2 = x + ctx @ Wo
    dim3 gq(Dm / 128, TOK / 128);
    gemm_hmma<<<gq, 256, GH_SMEM>>>(p_cxh, p_cxl, woh, wol, x, p_x2, TOK, Dm, Dm, Dm,
                                    nullptr, nullptr, 0);

    // 6. h2 = rmsnorm(x2) -> bf16 split
    rmsnorm_k<<<TOK, 256>>>(p_x2, ffn_w, p_hh, p_hl);

    // 7. fused w1|w2 GEMM with SwiGLU epilogue -> s1 (bf16 split)
    gemm_hmma<<<dim3(2*Ff/128, TOK/128), 256, GH_SMEM>>>(
        p_hh, p_hl, w12h, w12l, nullptr, nullptr, TOK, 2*Ff, 0, Dm,
        p_s1h, p_s1l, 1);

    // 8. out = x2 + (silu(a1)*a2) @ w3
    gemm_hmma<<<gq, 256, GH_SMEM>>>(p_s1h, p_s1l, w3h, w3l, p_x2, out, TOK, Dm, Dm, Ff,
                                    nullptr, nullptr, 0);
}

// round 6
// speedup vs baseline: 2.7379x; 1.0185x over previous
#include <cuda_runtime.h>
#include <cuda_bf16.h>
#include <math.h>
#include <math_constants.h>
#include <stdint.h>

#define TOK 4096   // B*S
#define Dm  1024
#define Hh  16
#define HDim 64
#define Ff  4096
#define Ss  2048
#define NQKV 3200  // q(1024) k(1024) v(1024) router(64) pad(64)

// ---------------- fp32 scratch ----------------------------------------------
__device__ float g_qkvr[TOK*NQKV];
__device__ float g_x2 [TOK*Dm];
__device__ int   g_node[TOK*Hh];
__device__ float g_pos [TOK*Hh];
__device__ int   g_start [32*4];
__device__ int   g_qstart[32*Ss];
__device__ int   g_orig  [32*Ss];
__device__ float g_qp[32*Ss*HDim];
__device__ float g_kp[32*Ss*HDim];
__device__ float g_vp[32*Ss*HDim];

// ---------------- bf16 split activations ------------------------------------
__device__ __nv_bfloat16 g_hh [TOK*Dm], g_hl [TOK*Dm];
__device__ __nv_bfloat16 g_cxh[TOK*Dm], g_cxl[TOK*Dm];
__device__ __nv_bfloat16 g_s1h[TOK*Ff], g_s1l[TOK*Ff];

// ---------------- bf16 split transposed weights [N,K] -----------------------
__device__ __nv_bfloat16 g_wAh[NQKV*Dm], g_wAl[NQKV*Dm];    // Wq|Wk|Wv|Wr|0
__device__ __nv_bfloat16 g_woh[Dm*Dm],   g_wol[Dm*Dm];
__device__ __nv_bfloat16 g_w12h[2*Ff*Dm], g_w12l[2*Ff*Dm];  // w1/w2 interleaved by 64-col group
__device__ __nv_bfloat16 g_w3h[Dm*Ff],   g_w3l[Dm*Ff];

// ---------------- helpers -----------------------------------------------------
__device__ __forceinline__ uint32_t s2u(const void* p) {
    uint32_t a;
    asm("{ .reg .u64 t; cvta.to.shared.u64 t, %1; cvt.u32.u64 %0, t; }" : "=r"(a) : "l"(p));
    return a;
}

#define LDSM4(r, addr) \
    asm volatile("ldmatrix.sync.aligned.m8n8.x4.shared.b16 {%0,%1,%2,%3}, [%4];" \
        : "=r"((r)[0]), "=r"((r)[1]), "=r"((r)[2]), "=r"((r)[3]) : "r"(addr))

#define MMA(d, a, b) \
    asm volatile("mma.sync.aligned.m16n8k16.row.col.f32.bf16.bf16.f32 " \
        "{%0,%1,%2,%3}, {%4,%5,%6,%7}, {%8,%9}, {%0,%1,%2,%3};" \
        : "+f"((d)[0]), "+f"((d)[1]), "+f"((d)[2]), "+f"((d)[3]) \
        : "r"((a)[0]), "r"((a)[1]), "r"((a)[2]), "r"((a)[3]), "r"((b)[0]), "r"((b)[1]))

#define CPASYNC(dst, src) \
    asm volatile("cp.async.cg.shared.global [%0], [%1], 16;" :: "r"(dst), "l"(src))

// ---------------- fast exp (FMA pipe only) ----------------------------------
__device__ __forceinline__ float fexp(float x) {
    x = fminf(fmaxf(x, -87.0f), 88.0f);
    float y = x * 1.4426950408889634f;
    float n = rintf(y);
    float f = y - n;
    float p = 1.3333558146e-3f;
    p = fmaf(p, f, 9.6181291076e-3f);
    p = fmaf(p, f, 5.5504108665e-2f);
    p = fmaf(p, f, 2.4022650696e-1f);
    p = fmaf(p, f, 6.9314718056e-1f);
    p = fmaf(p, f, 1.0f);
    return p * __int_as_float(((int)n + 127) << 23);
}

// ---------------- HMMA split-bf16 GEMM, 2-stage, 2 CTAs/SM -------------------
// swiglu==0: C[M,Nc](ldc) = A@B^T (+R)
// swiglu==1: tile = one 64-col group g=blockIdx.x of interleaved w1|w2;
//            writes silu(a1)*a2 (bf16 split) to Oh/Ol[M,Ff]
#define BUF_BYTES 40960
#define GH_SMEM   (2 * BUF_BYTES)

__global__ __launch_bounds__(256, 2)
void gemm_hmma(const __nv_bfloat16* __restrict__ Ah, const __nv_bfloat16* __restrict__ Al,
               const __nv_bfloat16* __restrict__ Bh, const __nv_bfloat16* __restrict__ Bl,
               const float* __restrict__ R, float* __restrict__ C,
               int M, int Nc, int ldc, int K,
               __nv_bfloat16* __restrict__ Oh, __nv_bfloat16* __restrict__ Ol, int swiglu) {
    extern __shared__ char smraw[];
    const int tid  = threadIdx.x;
    const int lane = tid & 31, wid = tid >> 5;
    const int m0 = blockIdx.y * 128, n0 = blockIdx.x * 128;
    const int warp_m = (wid >> 2) * 64, warp_n = (wid & 3) * 32;
    const int nc = K >> 5;
    const uint32_t sb = s2u(smraw);

    const char* gA  = (const char*)Ah + (size_t)m0 * K * 2;
    const char* gAl = (const char*)Al + (size_t)m0 * K * 2;
    const char* gB  = (const char*)Bh + (size_t)n0 * K * 2;
    const char* gBl = (const char*)Bl + (size_t)n0 * K * 2;

    int lr0 = tid >> 2,          lc0 = (tid & 3) * 16;
    int lr1 = (tid + 256) >> 2,  lc1 = lc0;

    #define ISSUE(buf, kc) do { \
        uint32_t db = sb + (buf) * BUF_BYTES; \
        size_t ko = (size_t)(kc) * 64; \
        uint32_t so0 = lr0 * 80 + lc0, so1 = lr1 * 80 + lc1; \
        size_t go0 = (size_t)lr0 * (K * 2) + ko + lc0; \
        size_t go1 = (size_t)lr1 * (K * 2) + ko + lc1; \
        CPASYNC(db + so0,         gA  + go0); CPASYNC(db + so1,         gA  + go1); \
        CPASYNC(db + 10240 + so0, gAl + go0); CPASYNC(db + 10240 + so1, gAl + go1); \
        CPASYNC(db + 20480 + so0, gB  + go0); CPASYNC(db + 20480 + so1, gB  + go1); \
        CPASYNC(db + 30720 + so0, gBl + go0); CPASYNC(db + 30720 + so1, gBl + go1); \
        asm volatile("cp.async.commit_group;"); \
    } while (0)

    ISSUE(0, 0);
    ISSUE(1, 1);

    float acc[4][4][4];
    #pragma unroll
    for (int i = 0; i < 4; i++)
        #pragma unroll
        for (int j = 0; j < 4; j++)
            #pragma unroll
            for (int q = 0; q < 4; q++) acc[i][j][q] = 0.f;

    const int a_row = (lane & 7) + ((lane >> 3) & 1) * 8;
    const int a_cb  = (lane >> 4) * 16;
    const int b_row = (lane & 7) + (lane >> 4) * 8;
    const int b_cb  = ((lane >> 3) & 1) * 16;
    // hoisted per-warp lane offsets within a buffer
    const uint32_t aoff = (warp_m + a_row) * 80 + a_cb;
    const uint32_t boff = 20480 + (warp_n + b_row) * 80 + b_cb;

    #pragma unroll 1
    for (int kc = 0; kc < nc; kc++) {
        if (kc + 1 < nc) asm volatile("cp.async.wait_group 1;");
        else             asm volatile("cp.async.wait_group 0;");
        __syncthreads();
        uint32_t db = sb + (kc & 1) * BUF_BYTES;
        #pragma unroll
        for (int ks = 0; ks < 2; ks++) {
            // phase 1: ah, bh, bl live (peak 32 frag regs)
            uint32_t ah[4][4], bh[4][2], bl[4][2];
            #pragma unroll
            for (int mt = 0; mt < 4; mt++)
                LDSM4(ah[mt], db + aoff + mt * (16 * 80) + ks * 32);
            #pragma unroll
            for (int p = 0; p < 2; p++) {
                uint32_t bd = db + boff + p * (16 * 80) + ks * 32;
                LDSM4(&bh[2 * p][0], bd);
                LDSM4(&bl[2 * p][0], bd + 10240);
            }
            #pragma unroll
            for (int mt = 0; mt < 4; mt++)
                #pragma unroll
                for (int nt = 0; nt < 4; nt++) MMA(acc[mt][nt], ah[mt], bh[nt]);
            #pragma unroll
            for (int mt = 0; mt < 4; mt++)
                #pragma unroll
                for (int nt = 0; nt < 4; nt++) MMA(acc[mt][nt], ah[mt], bl[nt]);
            // phase 2: ah dead; load al (reuses pressure budget), bl dead after use above
            uint32_t al[4][4];
            #pragma unroll
            for (int mt = 0; mt < 4; mt++)
                LDSM4(al[mt], db + aoff + mt * (16 * 80) + ks * 32 + 10240);
            #pragma unroll
            for (int mt = 0; mt < 4; mt++)
                #pragma unroll
                for (int nt = 0; nt < 4; nt++) MMA(acc[mt][nt], al[mt], bh[nt]);
        }
        __syncthreads();
        if (kc + 2 < nc) ISSUE(kc & 1, kc + 2);
    }
    #undef ISSUE

    const int g  = lane >> 2;
    const int cc = (lane & 3) * 2;

    if (swiglu) {
        float* sm2 = (float*)smraw;          // [128][68] fp32 staging for a2
        if ((wid & 3) >= 2) {
            #pragma unroll
            for (int mt = 0; mt < 4; mt++) {
                int row0 = warp_m + mt * 16 + g;
                #pragma unroll
                for (int nt = 0; nt < 4; nt++) {
                    int c = warp_n - 64 + nt * 8 + cc;
                    sm2[row0 * 68 + c]           = acc[mt][nt][0];
                    sm2[row0 * 68 + c + 1]       = acc[mt][nt][1];
                    sm2[(row0 + 8) * 68 + c]     = acc[mt][nt][2];
                    sm2[(row0 + 8) * 68 + c + 1] = acc[mt][nt][3];
                }
            }
        }
        __syncthreads();
        if ((wid & 3) < 2) {
            size_t colbase = (size_t)blockIdx.x * 64;
            #pragma unroll
            for (int mt = 0; mt < 4; mt++) {
                #pragma unroll
                for (int rr = 0; rr < 2; rr++) {
                    int row = warp_m + mt * 16 + g + rr * 8;
                    size_t orow = (size_t)(m0 + row) * Ff + colbase;
                    #pragma unroll
                    for (int nt = 0; nt < 4; nt++) {
                        int c = warp_n + nt * 8 + cc;
                        float a1a = acc[mt][nt][rr * 2], a1b = acc[mt][nt][rr * 2 + 1];
                        float a2a = sm2[row * 68 + c], a2b = sm2[row * 68 + c + 1];
                        float r0 = a1a / (1.f + fexp(-a1a)) * a2a;
                        float r1 = a1b / (1.f + fexp(-a1b)) * a2b;
                        __nv_bfloat16 h0 = __float2bfloat16(r0), h1 = __float2bfloat16(r1);
                        __nv_bfloat162 H; H.x = h0; H.y = h1;
                        *(__nv_bfloat162*)(Oh + orow + c) = H;
                        __nv_bfloat162 L;
                        L.x = __float2bfloat16(r0 - __bfloat162float(h0));
                        L.y = __float2bfloat16(r1 - __bfloat162float(h1));
                        *(__nv_bfloat162*)(Ol + orow + c) = L;
                    }
                }
            }
        }
        return;
    }

    #pragma unroll
    for (int mt = 0; mt < 4; mt++) {
        int row0 = m0 + warp_m + mt * 16 + g;
        #pragma unroll
        for (int nt = 0; nt < 4; nt++) {
            int col = n0 + warp_n + nt * 8 + cc;
            if (col < Nc) {
                float2 v0 = make_float2(acc[mt][nt][0], acc[mt][nt][1]);
                float2 v1 = make_float2(acc[mt][nt][2], acc[mt][nt][3]);
                if (R) {
                    float2 r0 = *(const float2*)(R + (size_t)row0 * ldc + col);
                    float2 r1 = *(const float2*)(R + (size_t)(row0 + 8) * ldc + col);
                    v0.x += r0.x; v0.y += r0.y; v1.x += r1.x; v1.y += r1.y;
                }
                *(float2*)(C + (size_t)row0 * ldc + col)       = v0;
                *(float2*)(C + (size_t)(row0 + 8) * ldc + col) = v1;
            }
        }
    }
}

// ---------------- weight transpose + bf16 split (+ optional row remap) -------
__global__ void wsplit_k(const float* __restrict__ W, __nv_bfloat16* __restrict__ Th,
                         __nv_bfloat16* __restrict__ Tl, int Kd, int Nd, int mode) {
    __shared__ float t[32][33];
    int n0 = blockIdx.x * 32, k0 = blockIdx.y * 32;
    int tx = threadIdx.x, ty = threadIdx.y;
    #pragma unroll
    for (int i = 0; i < 4; i++)
        t[ty + i * 8][tx] = W[(size_t)(k0 + ty + i * 8) * Nd + n0 + tx];
    __syncthreads();
    #pragma unroll
    for (int i = 0; i < 4; i++) {
        int r = ty + i * 8;
        int n = n0 + r;
        size_t orow = (mode == 0) ? (size_t)n
                    : (size_t)((n >> 6) * 128 + (n & 63) + ((mode == 2) ? 64 : 0));
        float v = t[tx][r];
        __nv_bfloat16 hb = __float2bfloat16(v);
        size_t o = orow * Kd + k0 + tx;
        Th[o] = hb;
        Tl[o] = __float2bfloat16(v - __bfloat162float(hb));
    }
}

// ---------------- rmsnorm -> bf16 split --------------------------------------
__global__ void rmsnorm_k(const float* __restrict__ x, const float* __restrict__ w,
                          __nv_bfloat16* __restrict__ oh, __nv_bfloat16* __restrict__ ol) {
    int row = blockIdx.x;
    const float4* xr = (const float4*)(x + (size_t)row * Dm);
    float4 v = xr[threadIdx.x];
    float ss = v.x*v.x + v.y*v.y + v.z*v.z + v.w*v.w;
    #pragma unroll
    for (int o = 16; o; o >>= 1) ss += __shfl_xor_sync(0xffffffffu, ss, o);
    __shared__ float sws[8];
    int lane = threadIdx.x & 31, wid = threadIdx.x >> 5;
    if (lane == 0) sws[wid] = ss;
    __syncthreads();
    if (threadIdx.x == 0) {
        float t = 0.f;
        #pragma unroll
        for (int i = 0; i < 8; i++) t += sws[i];
        sws[0] = rsqrtf(t * (1.0f / Dm) + 1e-6f);
    }
    __syncthreads();
    float inv = sws[0];
    float4 wv = ((const float4*)w)[threadIdx.x];
    float4 o4;
    o4.x = v.x * inv * wv.x; o4.y = v.y * inv * wv.y;
    o4.z = v.z * inv * wv.z; o4.w = v.w * inv * wv.w;
    __nv_bfloat16 h0 = __float2bfloat16(o4.x), h1 = __float2bfloat16(o4.y);
    __nv_bfloat16 h2 = __float2bfloat16(o4.z), h3 = __float2bfloat16(o4.w);
    __nv_bfloat162 H0; H0.x = h0; H0.y = h1;
    __nv_bfloat162 H1; H1.x = h2; H1.y = h3;
    __nv_bfloat162* ph = (__nv_bfloat162*)(oh + (size_t)row * Dm);
    ph[threadIdx.x * 2]     = H0;
    ph[threadIdx.x * 2 + 1] = H1;
    __nv_bfloat162 L0, L1;
    L0.x = __float2bfloat16(o4.x - __bfloat162float(h0));
    L0.y = __float2bfloat16(o4.y - __bfloat162float(h1));
    L1.x = __float2bfloat16(o4.z - __bfloat162float(h2));
    L1.y = __float2bfloat16(o4.w - __bfloat162float(h3));
    __nv_bfloat162* pl = (__nv_bfloat162*)(ol + (size_t)row * Dm);
    pl[threadIdx.x * 2]     = L0;
    pl[threadIdx.x * 2 + 1] = L1;
}

// ---------------- node/pos + partition starts --------------------------------
__global__ void node_pos_k() {
    int bh = blockIdx.x;
    int b = bh >> 4, h = bh & 15;
    int t = threadIdx.x;
    __shared__ int cnts[256][4];
    __shared__ int base[256][4];
    int myn[8], posl[8];
    int local[4] = {0, 0, 0, 0};
    #pragma unroll
    for (int j = 0; j < 8; j++) {
        int s = t * 8 + j;
        int tok = b * Ss + s;
        const float* lp = g_qkvr + (size_t)tok * NQKV + 3072 + h * 4;
        float l0 = lp[0], l1 = lp[1], l2 = lp[2], l3 = lp[3];
        int n = 0; float bv = l0;
        if (l1 > bv) { bv = l1; n = 1; }
        if (l2 > bv) { bv = l2; n = 2; }
        if (l3 > bv) { bv = l3; n = 3; }
        myn[j] = n;
        posl[j] = local[n];
        local[n]++;
    }
    cnts[t][0] = local[0]; cnts[t][1] = local[1];
    cnts[t][2] = local[2]; cnts[t][3] = local[3];
    __syncthreads();
    if (t == 0) {
        int run[4] = {0, 0, 0, 0};
        for (int i = 0; i < 256; i++)
            #pragma unroll
            for (int v = 0; v < 4; v++) { base[i][v] = run[v]; run[v] += cnts[i][v]; }
        int st = 0;
        #pragma unroll
        for (int v = 0; v < 4; v++) { g_start[bh * 4 + v] = st; st += run[v]; }
    }
    __syncthreads();
    #pragma unroll
    for (int j = 0; j < 8; j++) {
        int s = t * 8 + j;
        int tok = b * Ss + s;
        int n = myn[j];
        g_node[tok * Hh + h] = n;
        g_pos[tok * Hh + h] = (float)(base[t][n] + posl[j]);
    }
}

// ---------------- permute (node partition) + RoPE ----------------------------
__global__ void permute_k() {
    int inst = blockIdx.x * 4 + (threadIdx.x >> 5);   // tok*16 + h
    int lane = threadIdx.x & 31;
    int tok = inst >> 4, h = inst & 15;
    int b = tok >> 11;
    int bh = b * 16 + h;
    int n = g_node[tok * Hh + h];
    float pos = g_pos[tok * Hh + h];
    int startn = g_start[bh * 4 + n];
    int slot = startn + (int)pos;
    const float* src = g_qkvr + (size_t)tok * NQKV;
    float invf = exp2f(-(float)lane * (13.287712379549449f / 32.0f));
    float ang = pos * invf;
    float s, c;
    sincosf(ang, &s, &c);
    size_t drow = ((size_t)bh * Ss + slot) * HDim;
    float q1 = src[h * 64 + lane], q2 = src[h * 64 + lane + 32];
    g_qp[drow + lane]      = q1 * c - q2 * s;
    g_qp[drow + lane + 32] = q2 * c + q1 * s;
    float k1 = src[1024 + h * 64 + lane], k2 = src[1024 + h * 64 + lane + 32];
    g_kp[drow + lane]      = k1 * c - k2 * s;
    g_kp[drow + lane + 32] = k2 * c + k1 * s;
    g_vp[drow + lane]      = src[2048 + h * 64 + lane];
    g_vp[drow + lane + 32] = src[2048 + h * 64 + lane + 32];
    if (lane == 0) {
        g_qstart[bh * Ss + slot] = startn;
        g_orig  [bh * Ss + slot] = tok;
    }
}

// ---------------- attention: dense per-partition causal flash ----------------
#define ATTN_SMEM ((4096 + 4096 + 128 * 65) * 4)
__global__ __launch_bounds__(128)
void attn_k() {
    int bh = blockIdx.y;
    int h = bh & 15;
    int q0 = blockIdx.x * 128;
    int tid = threadIdx.x;
    int j = q0 + tid;                       // slot
    size_t base = (size_t)bh * Ss;
    extern __shared__ float sm[];
    float* Ks = sm;
    float* Vs = sm + 4096;
    float* Sc = sm + 8192;

    float qreg[64];
    const float4* qp = (const float4*)(g_qp + (base + j) * HDim);
    #pragma unroll
    for (int d4 = 0; d4 < 16; d4++) {
        float4 v = qp[d4];
        qreg[d4*4+0] = v.x; qreg[d4*4+1] = v.y; qreg[d4*4+2] = v.z; qreg[d4*4+3] = v.w;
    }
    int startq = g_qstart[base + j];
    int orig   = g_orig[base + j];
    int kt0 = g_qstart[base + q0] >> 6;
    int ktE = (q0 >> 6) + 2;

    float m = -CUDART_INF_F, l = 0.f;
    float acc[64];
    #pragma unroll
    for (int d = 0; d < 64; d++) acc[d] = 0.f;

    for (int kt = kt0; kt < ktE; ++kt) {
        int kb = kt * 64;
        __syncthreads();
        for (int e = tid; e < 1024; e += 128) {
            int r = e >> 4, c = (e & 15) * 4;
            size_t srow = (base + kb + r) * HDim;
            *(float4*)&Ks[r * 64 + c] = *(const float4*)(g_kp + srow + c);
            *(float4*)&Vs[r * 64 + c] = *(const float4*)(g_vp + srow + c);
        }
        __syncthreads();

        float tmax = -CUDART_INF_F;
        #pragma unroll 1
        for (int kk = 0; kk < 64; ++kk) {
            int ki = kb + kk;
            float s = -1e30f;
            if (ki >= startq && ki <= j) {
                float s0 = 0.f, s1 = 0.f, s2 = 0.f, s3 = 0.f;
                const float4* kr = (const float4*)&Ks[kk * 64];
                #pragma unroll
                for (int d4 = 0; d4 < 16; d4++) {
                    float4 kv = kr[d4];
                    s0 = fmaf(qreg[d4*4+0], kv.x, s0);
                    s1 = fmaf(qreg[d4*4+1], kv.y, s1);
                    s2 = fmaf(qreg[d4*4+2], kv.z, s2);
                    s3 = fmaf(qreg[d4*4+3], kv.w, s3);
                }
                s = ((s0 + s1) + (s2 + s3)) * 0.125f;
            }
            Sc[tid * 65 + kk] = s;
            tmax = fmaxf(tmax, s);
        }
        if (tmax > -1e29f) {
            float nm = fmaxf(m, tmax);
            float scl = fexp(m - nm);
            l *= scl;
            #pragma unroll
            for (int d = 0; d < 64; d++) acc[d] *= scl;
            #pragma unroll 1
            for (int kk = 0; kk < 64; ++kk) {
                float p = fexp(Sc[tid * 65 + kk] - nm);
                l += p;
                const float4* vr = (const float4*)&Vs[kk * 64];
                #pragma unroll
                for (int d4 = 0; d4 < 16; d4++) {
                    float4 vv = vr[d4];
                    acc[d4*4+0] = fmaf(p, vv.x, acc[d4*4+0]);
                    acc[d4*4+1] = fmaf(p, vv.y, acc[d4*4+1]);
                    acc[d4*4+2] = fmaf(p, vv.z, acc[d4*4+2]);
                    acc[d4*4+3] = fmaf(p, vv.w, acc[d4*4+3]);
                }
            }
            m = nm;
        }
    }
    float inv = 1.f / l;
    __nv_bfloat162* oh = (__nv_bfloat162*)(g_cxh + (size_t)orig * Dm + h * HDim);
    __nv_bfloat162* ol = (__nv_bfloat162*)(g_cxl + (size_t)orig * Dm + h * HDim);
    #pragma unroll
    for (int d2 = 0; d2 < 32; d2++) {
        float v0 = acc[d2*2] * inv, v1 = acc[d2*2+1] * inv;
        __nv_bfloat16 h0 = __float2bfloat16(v0), h1 = __float2bfloat16(v1);
        __nv_bfloat162 H; H.x = h0; H.y = h1;
        oh[d2] = H;
        __nv_bfloat162 L;
        L.x = __float2bfloat16(v0 - __bfloat162float(h0));
        L.y = __float2bfloat16(v1 - __bfloat162float(h1));
        ol[d2] = L;
    }
}

// ---------------- host launcher ----------------------------------------------
#define SYM(p, s) do { void* _t; cudaGetSymbolAddress(&_t, s); p = (decltype(p))_t; } while (0)

extern "C" void kernel_launch(void* const* d_in, const int* in_sizes, int n_in,
                              void* d_out, int out_size) {
    const float* x      = (const float*)d_in[0];
    const float* attn_w = (const float*)d_in[1];
    const float* ffn_w  = (const float*)d_in[2];
    const float* Wq     = (const float*)d_in[3];
    const float* Wk     = (const float*)d_in[4];
    const float* Wv     = (const float*)d_in[5];
    const float* Wo     = (const float*)d_in[6];
    const float* Wr     = (const float*)d_in[7];
    const float* w1     = (const float*)d_in[8];
    const float* w2     = (const float*)d_in[9];
    const float* w3     = (const float*)d_in[10];
    float* out = (float*)d_out;

    float *p_qkvr, *p_x2;
    SYM(p_qkvr, g_qkvr); SYM(p_x2, g_x2);
    __nv_bfloat16 *p_hh, *p_hl, *p_cxh, *p_cxl, *p_s1h, *p_s1l;
    SYM(p_hh, g_hh); SYM(p_hl, g_hl); SYM(p_cxh, g_cxh); SYM(p_cxl, g_cxl);
    SYM(p_s1h, g_s1h); SYM(p_s1l, g_s1l);
    __nv_bfloat16 *wAh, *wAl, *woh, *wol, *w12h, *w12l, *w3h, *w3l;
    SYM(wAh, g_wAh); SYM(wAl, g_wAl); SYM(woh, g_woh); SYM(wol, g_wol);
    SYM(w12h, g_w12h); SYM(w12l, g_w12l); SYM(w3h, g_w3h); SYM(w3l, g_w3l);

    cudaFuncSetAttribute(attn_k, cudaFuncAttributeMaxDynamicSharedMemorySize, ATTN_SMEM);
    cudaFuncSetAttribute(gemm_hmma, cudaFuncAttributeMaxDynamicSharedMemorySize, GH_SMEM);

    // zero pad rows [3136, 3200) of fused A-weights
    cudaMemsetAsync(wAh + (size_t)3136 * Dm, 0, 64 * Dm * sizeof(__nv_bfloat16));
    cudaMemsetAsync(wAl + (size_t)3136 * Dm, 0, 64 * Dm * sizeof(__nv_bfloat16));

    dim3 tb(32, 8);
    wsplit_k<<<dim3(Dm/32, Dm/32), tb>>>(Wq, wAh,           wAl,           Dm, Dm, 0);
    wsplit_k<<<dim3(Dm/32, Dm/32), tb>>>(Wk, wAh + 1024*Dm, wAl + 1024*Dm, Dm, Dm, 0);
    wsplit_k<<<dim3(Dm/32, Dm/32), tb>>>(Wv, wAh + 2048*Dm, wAl + 2048*Dm, Dm, Dm, 0);
    wsplit_k<<<dim3(2,     Dm/32), tb>>>(Wr, wAh + 3072*Dm, wAl + 3072*Dm, Dm, 64, 0);
    wsplit_k<<<dim3(Dm/32, Dm/32), tb>>>(Wo, woh, wol, Dm, Dm, 0);
    wsplit_k<<<dim3(Ff/32, Dm/32), tb>>>(w1, w12h, w12l, Dm, Ff, 1);
    wsplit_k<<<dim3(Ff/32, Dm/32), tb>>>(w2, w12h, w12l, Dm, Ff, 2);
    wsplit_k<<<dim3(Dm/32, Ff/32), tb>>>(w3, w3h, w3l, Ff, Dm, 0);

    // 1. h = rmsnorm(x) -> bf16 split
    rmsnorm_k<<<TOK, 256>>>(x, attn_w, p_hh, p_hl);

    // 2. fused q|k|v|router GEMM
    gemm_hmma<<<dim3(NQKV/128, TOK/128), 256, GH_SMEM>>>(
        p_hh, p_hl, wAh, wAl, nullptr, p_qkvr, TOK, NQKV, NQKV, Dm,
        nullptr, nullptr, 0);

    // 3. node/pos + partition & rope
    node_pos_k<<<32, 256>>>();
    permute_k<<<TOK * Hh / 4, 128>>>();

    // 4. partitioned causal flash attention -> ctx (bf16 split)
    attn_k<<<dim3(Ss / 128, 2 * Hh), 128, ATTN_SMEM>>>();

    // 5. x2 = x + ctx @ Wo
    dim3 gq(Dm / 128, TOK / 128);
    gemm_hmma<<<gq, 256, GH_SMEM>>>(p_cxh, p_cxl, woh, wol, x, p_x2, TOK, Dm, Dm, Dm,
                                    nullptr, nullptr, 0);

    // 6. h2 = rmsnorm(x2) -> bf16 split
    rmsnorm_k<<<TOK, 256>>>(p_x2, ffn_w, p_hh, p_hl);

    // 7. fused w1|w2 GEMM with SwiGLU epilogue -> s1 (bf16 split)
    gemm_hmma<<<dim3(2*Ff/128, TOK/128), 256, GH_SMEM>>>(
        p_hh, p_hl, w12h, w12l, nullptr, nullptr, TOK, 2*Ff, 0, Dm,
        p_s1h, p_s1l, 1);

    // 8. out = x2 + (silu(a1)*a2) @ w3
    gemm_hmma<<<gq, 256, GH_SMEM>>>(p_s1h, p_s1l, w3h, w3l, p_x2, out, TOK, Dm, Dm, Ff,
                                    nullptr, nullptr, 0);
}